// round 3
// baseline (speedup 1.0000x reference)
#include <cuda_runtime.h>
#include <cuda_bf16.h>
#include <math.h>

// ---------------- problem constants ----------------
#define BATCH   4
#define SEQ     2048
#define HID     512
#define DFF     2048
#define NLAYER  4
#define NHEAD   4
#define DHEAD   128
#define WINDOW  606
#define KTRUE   30
#define NTOK    (BATCH*SEQ)          // 8192
#define LN_EPS  1e-5f

// ---------------- scratch (static device memory; no runtime alloc) ----------------
__device__ float g_x   [NTOK*HID];
__device__ float g_qkv [NTOK*3*HID];
__device__ float g_attn[NTOK*HID];
__device__ float g_mid [NTOK*DFF];
__device__ float g_t2  [NTOK*HID];
__device__ float g_small[NTOK*16];
__device__ float g_yhat[NTOK*8];

__device__ __forceinline__ float gelu_exact(float v) {
    return 0.5f * v * (1.0f + erff(v * 0.7071067811865475f));
}

// ---------------- embed: u_aug @ W_in + b_in + pos_enc ----------------
__global__ void embed_kernel(const float* __restrict__ u, const float* __restrict__ y,
                             const float* __restrict__ W_in, const float* __restrict__ b_in,
                             float* __restrict__ x) {
    int n = blockIdx.x;
    int c = threadIdx.x;
    int b = n >> 11;
    int t = n & (SEQ - 1);
    __shared__ float ua[24];
    if (c < 8)       ua[c] = u[(size_t)(b*8 + c)*SEQ + t];
    else if (c < 16) ua[c] = 0.0f;
    else if (c < 24) ua[c] = (t < KTRUE) ? y[(size_t)(b*8 + (c-16))*SEQ + t] : 0.0f;
    __syncthreads();
    float s = b_in[c];
    #pragma unroll
    for (int k = 0; k < 24; k++) s = fmaf(ua[k], W_in[k*HID + c], s);
    int i2 = c & ~1;
    float div = __expf(-9.210340371976184f * (float)i2 / (float)HID);
    float ang = (float)t * div;
    s += (c & 1) ? cosf(ang) : sinf(ang);
    x[(size_t)n*HID + c] = s;
}

// ---------------- big GEMM: 128x128 tile, 8x8 micro-tile ----------------
// Requires: M % 128 == 0, N % 128 == 0, K % 16 == 0
#define GBM 128
#define GBN 128
#define GBK 16
__global__ __launch_bounds__(256) void gemm128_kernel(
    const float* __restrict__ A, const float* __restrict__ W,
    const float* __restrict__ bias, float* __restrict__ C,
    int M, int N, int K, int epi) {
    __shared__ float As[GBK][GBM + 4];
    __shared__ float Bs[GBK][GBN + 4];
    const int bm = blockIdx.y * GBM;
    const int bn = blockIdx.x * GBN;
    const int tid = threadIdx.x;
    const int tx = tid & 15, ty = tid >> 4;
    const int arow = tid >> 1;
    const int ak = (tid & 1) * 4;
    const int br = tid >> 5;            // 0..7
    const int bc = (tid & 31) * 4;      // 0..124

    float acc[8][8];
    #pragma unroll
    for (int i = 0; i < 8; i++)
        #pragma unroll
        for (int j = 0; j < 8; j++) acc[i][j] = 0.0f;

    for (int kk = 0; kk < K; kk += GBK) {
        float4 a0 = *(const float4*)(A + (size_t)(bm + arow)*K + kk + ak);
        float4 a1 = *(const float4*)(A + (size_t)(bm + arow)*K + kk + ak + 8);
        As[ak+0][arow] = a0.x; As[ak+1][arow] = a0.y; As[ak+2][arow] = a0.z; As[ak+3][arow] = a0.w;
        As[ak+8][arow] = a1.x; As[ak+9][arow] = a1.y; As[ak+10][arow] = a1.z; As[ak+11][arow] = a1.w;
        *(float4*)&Bs[br][bc]     = *(const float4*)(W + (size_t)(kk + br)*N + bn + bc);
        *(float4*)&Bs[br + 8][bc] = *(const float4*)(W + (size_t)(kk + br + 8)*N + bn + bc);
        __syncthreads();
        #pragma unroll
        for (int k = 0; k < GBK; k++) {
            float4 av0 = *(float4*)&As[k][ty*4];
            float4 av1 = *(float4*)&As[k][ty*4 + 64];
            float4 bv0 = *(float4*)&Bs[k][tx*4];
            float4 bv1 = *(float4*)&Bs[k][tx*4 + 64];
            float a[8] = {av0.x, av0.y, av0.z, av0.w, av1.x, av1.y, av1.z, av1.w};
            float b[8] = {bv0.x, bv0.y, bv0.z, bv0.w, bv1.x, bv1.y, bv1.z, bv1.w};
            #pragma unroll
            for (int i = 0; i < 8; i++)
                #pragma unroll
                for (int j = 0; j < 8; j++)
                    acc[i][j] = fmaf(a[i], b[j], acc[i][j]);
        }
        __syncthreads();
    }
    #pragma unroll
    for (int i = 0; i < 8; i++) {
        int row = bm + ty*4 + ((i < 4) ? i : 60 + i);   // ty*4+i or ty*4+64+(i-4)
        #pragma unroll
        for (int jj = 0; jj < 2; jj++) {
            int col = bn + tx*4 + jj*64;
            float4 r;
            r.x = acc[i][jj*4+0] + bias[col+0];
            r.y = acc[i][jj*4+1] + bias[col+1];
            r.z = acc[i][jj*4+2] + bias[col+2];
            r.w = acc[i][jj*4+3] + bias[col+3];
            if (epi == 1) {
                r.x = gelu_exact(r.x); r.y = gelu_exact(r.y);
                r.z = gelu_exact(r.z); r.w = gelu_exact(r.w);
            }
            *(float4*)(C + (size_t)row*N + col) = r;
        }
    }
}

// ---------------- small GEMM (64x64 tile) for N=16 / N=8 heads ----------------
#define BM 64
#define BN 64
#define BKT 16
__global__ __launch_bounds__(256) void gemm_kernel(
    const float* __restrict__ A, const float* __restrict__ W,
    const float* __restrict__ bias, float* __restrict__ C,
    int M, int N, int K, int epi) {
    __shared__ float As[BKT][BM + 4];
    __shared__ float Bs[BKT][BN];
    const int bm = blockIdx.y * BM;
    const int bn = blockIdx.x * BN;
    const int tid = threadIdx.x;
    const int tx = tid & 15, ty = tid >> 4;
    const int ar = tid >> 2;
    const int ak = (tid & 3) * 4;
    const int bk = tid >> 4;
    const int bc = (tid & 15) * 4;
    const bool nfull = (bn + BN <= N);

    float acc[4][4];
    #pragma unroll
    for (int i = 0; i < 4; i++)
        #pragma unroll
        for (int j = 0; j < 4; j++) acc[i][j] = 0.0f;

    for (int kk = 0; kk < K; kk += BKT) {
        float4 av = *(const float4*)(A + (size_t)(bm + ar)*K + kk + ak);
        As[ak+0][ar] = av.x; As[ak+1][ar] = av.y; As[ak+2][ar] = av.z; As[ak+3][ar] = av.w;
        if (nfull) {
            *(float4*)&Bs[bk][bc] = *(const float4*)(W + (size_t)(kk + bk)*N + bn + bc);
        } else {
            #pragma unroll
            for (int q = 0; q < 4; q++) {
                int cc = bn + bc + q;
                Bs[bk][bc+q] = (cc < N) ? W[(size_t)(kk + bk)*N + cc] : 0.0f;
            }
        }
        __syncthreads();
        #pragma unroll
        for (int k = 0; k < BKT; k++) {
            float a0 = As[k][ty*4+0], a1 = As[k][ty*4+1], a2 = As[k][ty*4+2], a3 = As[k][ty*4+3];
            float4 bv = *(float4*)&Bs[k][tx*4];
            acc[0][0] = fmaf(a0, bv.x, acc[0][0]); acc[0][1] = fmaf(a0, bv.y, acc[0][1]);
            acc[0][2] = fmaf(a0, bv.z, acc[0][2]); acc[0][3] = fmaf(a0, bv.w, acc[0][3]);
            acc[1][0] = fmaf(a1, bv.x, acc[1][0]); acc[1][1] = fmaf(a1, bv.y, acc[1][1]);
            acc[1][2] = fmaf(a1, bv.z, acc[1][2]); acc[1][3] = fmaf(a1, bv.w, acc[1][3]);
            acc[2][0] = fmaf(a2, bv.x, acc[2][0]); acc[2][1] = fmaf(a2, bv.y, acc[2][1]);
            acc[2][2] = fmaf(a2, bv.z, acc[2][2]); acc[2][3] = fmaf(a2, bv.w, acc[2][3]);
            acc[3][0] = fmaf(a3, bv.x, acc[3][0]); acc[3][1] = fmaf(a3, bv.y, acc[3][1]);
            acc[3][2] = fmaf(a3, bv.z, acc[3][2]); acc[3][3] = fmaf(a3, bv.w, acc[3][3]);
        }
        __syncthreads();
    }
    #pragma unroll
    for (int i = 0; i < 4; i++) {
        int row = bm + ty*4 + i;
        #pragma unroll
        for (int j = 0; j < 4; j++) {
            int col = bn + tx*4 + j;
            if (col < N) {
                float v = acc[i][j] + bias[col];
                if (epi == 1) v = gelu_exact(v);
                C[(size_t)row*N + col] = v;
            }
        }
    }
}

// ---------------- flash attention: 64-query tile per block, online softmax ----------------
#define QT 64
#define KC 32
#define QPAD 132
#define KPAD 132
#define SPAD 33
// smem floats: Q 64*132=8448, K 32*132=4224, V 32*128=4096, S 64*33=2112, rm/rl/rs 64*3=192
#define FL_Q  0
#define FL_K  8448
#define FL_V  (8448+4224)
#define FL_S  (8448+4224+4096)
#define FL_RM (FL_S+2112)
#define FL_RL (FL_RM+64)
#define FL_RS (FL_RL+64)
#define FL_FLOATS (FL_RS+64)
#define FLASH_SMEM (FL_FLOATS*4)

__global__ __launch_bounds__(256) void flash_kernel(const float* __restrict__ qkv,
                                                    float* __restrict__ out) {
    extern __shared__ float sm[];
    float* Qs = sm + FL_Q;
    float* Ks = sm + FL_K;
    float* Vs = sm + FL_V;
    float* Ss = sm + FL_S;
    float* rm = sm + FL_RM;
    float* rl = sm + FL_RL;
    float* rs = sm + FL_RS;

    const int tid = threadIdx.x;
    const int n0 = blockIdx.x * QT;        // first token of tile
    const int hh = blockIdx.y;
    const int t0 = n0 & (SEQ - 1);
    const int bb = n0 >> 11;

    // load Q tile (coalesced)
    #pragma unroll
    for (int q = 0; q < 8; q++) {
        int idx = tid + q*256;
        int r = idx >> 5, c = (idx & 31) * 4;
        float4 v = *(const float4*)(qkv + (size_t)(n0 + r)*(3*HID) + hh*DHEAD + c);
        *(float4*)&Qs[r*QPAD + c] = v;
    }
    if (tid < QT) { rm[tid] = -1e30f; rl[tid] = 0.0f; }

    float acc[8][4];
    #pragma unroll
    for (int i = 0; i < 8; i++)
        #pragma unroll
        for (int j = 0; j < 4; j++) acc[i][j] = 0.0f;

    const int rgs = tid >> 4, cgs = tid & 15;   // score: rows rgs*4.., cols cgs*2..
    const int rg2 = tid >> 5, cg2 = tid & 31;   // PV: rows rg2*8.., cols cg2*4..
    int jstart = t0 - (WINDOW - 1); if (jstart < 0) jstart = 0;
    const int tmax = t0 + QT - 1;
    __syncthreads();

    for (int jc = jstart; jc <= tmax; jc += KC) {
        // load K/V chunk (clamped rows; invalid keys masked in score phase)
        #pragma unroll
        for (int q = 0; q < 4; q++) {
            int idx = tid + q*256;
            int r = idx >> 5, c = (idx & 31) * 4;
            int ja = jc + r; if (ja > tmax) ja = tmax;
            const float* base = qkv + (size_t)((bb << 11) + ja)*(3*HID) + hh*DHEAD + c;
            *(float4*)&Ks[r*KPAD + c] = *(const float4*)(base + HID);
            *(float4*)&Vs[r*DHEAD + c] = *(const float4*)(base + 2*HID);
        }
        __syncthreads();

        // scores: 4 rows x 2 cols per thread
        float s[4][2];
        #pragma unroll
        for (int i = 0; i < 4; i++) { s[i][0] = 0.0f; s[i][1] = 0.0f; }
        #pragma unroll 4
        for (int k = 0; k < DHEAD; k += 4) {
            float4 k0 = *(float4*)&Ks[(cgs*2+0)*KPAD + k];
            float4 k1 = *(float4*)&Ks[(cgs*2+1)*KPAD + k];
            #pragma unroll
            for (int i = 0; i < 4; i++) {
                float4 qv = *(float4*)&Qs[(rgs*4+i)*QPAD + k];
                s[i][0] = fmaf(qv.x, k0.x, s[i][0]); s[i][0] = fmaf(qv.y, k0.y, s[i][0]);
                s[i][0] = fmaf(qv.z, k0.z, s[i][0]); s[i][0] = fmaf(qv.w, k0.w, s[i][0]);
                s[i][1] = fmaf(qv.x, k1.x, s[i][1]); s[i][1] = fmaf(qv.y, k1.y, s[i][1]);
                s[i][1] = fmaf(qv.z, k1.z, s[i][1]); s[i][1] = fmaf(qv.w, k1.w, s[i][1]);
            }
        }
        #pragma unroll
        for (int i = 0; i < 4; i++) {
            int tr = t0 + rgs*4 + i;
            #pragma unroll
            for (int j = 0; j < 2; j++) {
                int ja = jc + cgs*2 + j;
                bool ok = (ja <= tr) && (ja > tr - WINDOW);
                Ss[(rgs*4+i)*SPAD + cgs*2 + j] = ok ? s[i][j]*0.08838834764831845f : -1e30f;
            }
        }
        __syncthreads();

        // per-row online softmax (64 threads, one row each)
        if (tid < QT) {
            float m = rm[tid];
            float mc = m;
            float* srow = &Ss[tid*SPAD];
            #pragma unroll
            for (int j = 0; j < KC; j++) mc = fmaxf(mc, srow[j]);
            float l = 0.0f;
            #pragma unroll
            for (int j = 0; j < KC; j++) {
                float sv = srow[j];
                float p = (sv <= -1e29f) ? 0.0f : __expf(sv - mc);
                srow[j] = p; l += p;
            }
            float sc = __expf(m - mc);   // 0 if m was -inf-ish and mc real; 1 if unchanged
            rl[tid] = rl[tid]*sc + l;
            rm[tid] = mc;
            rs[tid] = sc;
        }
        __syncthreads();

        // rescale accumulators + P@V (8 rows x 4 cols per thread)
        #pragma unroll
        for (int i = 0; i < 8; i++) {
            float sc = rs[rg2*8 + i];
            acc[i][0] *= sc; acc[i][1] *= sc; acc[i][2] *= sc; acc[i][3] *= sc;
        }
        #pragma unroll 8
        for (int j = 0; j < KC; j++) {
            float4 vv = *(float4*)&Vs[j*DHEAD + cg2*4];
            #pragma unroll
            for (int i = 0; i < 8; i++) {
                float p = Ss[(rg2*8+i)*SPAD + j];
                acc[i][0] = fmaf(p, vv.x, acc[i][0]);
                acc[i][1] = fmaf(p, vv.y, acc[i][1]);
                acc[i][2] = fmaf(p, vv.z, acc[i][2]);
                acc[i][3] = fmaf(p, vv.w, acc[i][3]);
            }
        }
        __syncthreads();
    }

    #pragma unroll
    for (int i = 0; i < 8; i++) {
        int r = rg2*8 + i;
        float inv = 1.0f / rl[r];
        float4 o;
        o.x = acc[i][0]*inv; o.y = acc[i][1]*inv; o.z = acc[i][2]*inv; o.w = acc[i][3]*inv;
        *(float4*)(out + (size_t)(n0 + r)*HID + hh*DHEAD + cg2*4) = o;
    }
}

// ---------------- residual add + LayerNorm ----------------
__global__ __launch_bounds__(256) void ln_kernel(float* __restrict__ x,
                                                 const float* __restrict__ add,
                                                 const float* __restrict__ g,
                                                 const float* __restrict__ b) {
    const int n = blockIdx.x;
    const int tid = threadIdx.x;
    const int c0 = tid, c1 = tid + 256;
    float v0 = x[(size_t)n*HID + c0];
    float v1 = x[(size_t)n*HID + c1];
    if (add) { v0 += add[(size_t)n*HID + c0]; v1 += add[(size_t)n*HID + c1]; }
    float s  = v0 + v1;
    float sq = v0*v0 + v1*v1;
    #pragma unroll
    for (int o = 16; o > 0; o >>= 1) {
        s  += __shfl_xor_sync(0xffffffffu, s,  o);
        sq += __shfl_xor_sync(0xffffffffu, sq, o);
    }
    __shared__ float ss[8], qq[8];
    __shared__ float sh_mean, sh_rstd;
    int w = tid >> 5;
    if ((tid & 31) == 0) { ss[w] = s; qq[w] = sq; }
    __syncthreads();
    if (tid == 0) {
        float S = 0.0f, Q = 0.0f;
        #pragma unroll
        for (int i = 0; i < 8; i++) { S += ss[i]; Q += qq[i]; }
        float mean = S * (1.0f/512.0f);
        float var  = Q * (1.0f/512.0f) - mean*mean;
        sh_mean = mean;
        sh_rstd = rsqrtf(var + LN_EPS);
    }
    __syncthreads();
    float mean = sh_mean, rstd = sh_rstd;
    x[(size_t)n*HID + c0] = (v0 - mean) * rstd * g[c0] + b[c0];
    x[(size_t)n*HID + c1] = (v1 - mean) * rstd * g[c1] + b[c1];
}

// ---------------- loss ----------------
__global__ __launch_bounds__(1024) void loss_kernel(const float* __restrict__ yhat,
                                                    const float* __restrict__ y,
                                                    float* __restrict__ out) {
    float s = 0.0f;
    for (int e = threadIdx.x; e < NTOK*8; e += 1024) {
        int n = e >> 3, d = e & 7;
        int b = n >> 11, t = n & (SEQ - 1);
        float diff = yhat[e] - y[(size_t)(b*8 + d)*SEQ + t];
        s = fmaf(diff, diff, s);
    }
    #pragma unroll
    for (int o = 16; o > 0; o >>= 1) s += __shfl_xor_sync(0xffffffffu, s, o);
    __shared__ float red[32];
    int w = threadIdx.x >> 5;
    if ((threadIdx.x & 31) == 0) red[w] = s;
    __syncthreads();
    if (threadIdx.x == 0) {
        float tot = 0.0f;
        #pragma unroll
        for (int i = 0; i < 32; i++) tot += red[i];
        out[0] = tot;
    }
}

// ---------------- host orchestration ----------------
static inline void run_gemm128(const float* A, const float* W, const float* bias, float* C,
                               int M, int N, int K, int epi) {
    dim3 grid(N / GBN, M / GBM);
    gemm128_kernel<<<grid, 256>>>(A, W, bias, C, M, N, K, epi);
}
static inline void run_gemm_small(const float* A, const float* W, const float* bias, float* C,
                                  int M, int N, int K, int epi) {
    dim3 grid((N + BN - 1) / BN, M / BM);
    gemm_kernel<<<grid, 256>>>(A, W, bias, C, M, N, K, epi);
}

extern "C" void kernel_launch(void* const* d_in, const int* in_sizes, int n_in,
                              void* d_out, int out_size) {
    const float* u     = (const float*)d_in[0];
    const float* y     = (const float*)d_in[1];
    const float* W_in  = (const float*)d_in[2];
    const float* b_in  = (const float*)d_in[3];
    const float* qkv_w = (const float*)d_in[4];
    const float* qkv_b = (const float*)d_in[5];
    const float* out_w = (const float*)d_in[6];
    const float* out_b = (const float*)d_in[7];
    const float* ff1_w = (const float*)d_in[8];
    const float* ff1_b = (const float*)d_in[9];
    const float* ff2_w = (const float*)d_in[10];
    const float* ff2_b = (const float*)d_in[11];
    const float* ln1_g = (const float*)d_in[12];
    const float* ln1_b = (const float*)d_in[13];
    const float* ln2_g = (const float*)d_in[14];
    const float* ln2_b = (const float*)d_in[15];
    const float* lnf_g = (const float*)d_in[16];
    const float* lnf_b = (const float*)d_in[17];
    const float* xm1_w = (const float*)d_in[18];
    const float* xm1_b = (const float*)d_in[19];
    const float* xm2_w = (const float*)d_in[20];
    const float* xm2_b = (const float*)d_in[21];
    const float* me1_w = (const float*)d_in[22];
    const float* me1_b = (const float*)d_in[23];
    const float* me2_w = (const float*)d_in[24];
    const float* me2_b = (const float*)d_in[25];
    const float* me3_w = (const float*)d_in[26];
    const float* me3_b = (const float*)d_in[27];

    static float *px = nullptr, *pqkv, *pattn, *pmid, *pt2, *psmall, *pyhat;
    static bool attr_set = false;
    if (!px) {
        cudaGetSymbolAddress((void**)&px,    g_x);
        cudaGetSymbolAddress((void**)&pqkv,  g_qkv);
        cudaGetSymbolAddress((void**)&pattn, g_attn);
        cudaGetSymbolAddress((void**)&pmid,  g_mid);
        cudaGetSymbolAddress((void**)&pt2,   g_t2);
        cudaGetSymbolAddress((void**)&psmall,g_small);
        cudaGetSymbolAddress((void**)&pyhat, g_yhat);
    }
    if (!attr_set) {
        cudaFuncSetAttribute(flash_kernel, cudaFuncAttributeMaxDynamicSharedMemorySize, FLASH_SMEM);
        attr_set = true;
    }

    embed_kernel<<<NTOK, HID>>>(u, y, W_in, b_in, px);

    for (int l = 0; l < NLAYER; l++) {
        run_gemm128(px, qkv_w + (size_t)l*HID*3*HID, qkv_b + (size_t)l*3*HID, pqkv,
                    NTOK, 3*HID, HID, 0);
        flash_kernel<<<dim3(NTOK/QT, NHEAD), 256, FLASH_SMEM>>>(pqkv, pattn);
        run_gemm128(pattn, out_w + (size_t)l*HID*HID, out_b + (size_t)l*HID, pt2,
                    NTOK, HID, HID, 0);
        ln_kernel<<<NTOK, 256>>>(px, pt2, ln1_g + l*HID, ln1_b + l*HID);
        run_gemm128(px, ff1_w + (size_t)l*HID*DFF, ff1_b + (size_t)l*DFF, pmid,
                    NTOK, DFF, HID, 1);
        run_gemm128(pmid, ff2_w + (size_t)l*DFF*HID, ff2_b + (size_t)l*HID, pt2,
                    NTOK, HID, DFF, 0);
        ln_kernel<<<NTOK, 256>>>(px, pt2, ln2_g + l*HID, ln2_b + l*HID);
    }

    ln_kernel<<<NTOK, 256>>>(px, nullptr, lnf_g, lnf_b);

    run_gemm128(px,    xm1_w, xm1_b, pt2,    NTOK, HID, HID, 1);
    run_gemm_small(pt2, xm2_w, xm2_b, psmall, NTOK, 16,  HID, 0);
    run_gemm128(psmall, me1_w, me1_b, pt2,   NTOK, HID, 16,  1);
    run_gemm128(pt2,   me2_w, me2_b, pmid,   NTOK, HID, HID, 1);
    run_gemm_small(pmid, me3_w, me3_b, pyhat, NTOK, 8,  HID, 0);

    loss_kernel<<<1, 1024>>>(pyhat, y, (float*)d_out);
}

// round 6
// speedup vs baseline: 1.8779x; 1.8779x over previous
#include <cuda_runtime.h>
#include <cuda_bf16.h>
#include <mma.h>
#include <math.h>
#include <stdint.h>

using namespace nvcuda;

#define BATCH 4
#define SEQ   2048
#define HID   512
#define DFF   2048
#define NLAYER 4
#define NHEAD 4
#define DHEAD 128
#define WINDOW 606
#define KTRUE 30
#define NTOK  (BATCH*SEQ)
#define LN_EPS 1e-5f

// ---- scratch ----
__device__ float g_x[NTOK*HID];
__device__ float g_qkv[NTOK*3*HID];
__device__ float g_t2[NTOK*HID];
__device__ float g_small[NTOK*16];
__device__ float g_yhat[NTOK*8];
__device__ __nv_bfloat16 g_x16[NTOK*HID];
__device__ __nv_bfloat16 g_attn16[NTOK*HID];
__device__ __nv_bfloat16 g_mid16[NTOK*DFF];
// transposed bf16 weights [N,K]
#define OFF_QKV 0
#define OFF_OUT (OFF_QKV + 4*1536*512)
#define OFF_FF1 (OFF_OUT + 4*512*512)
#define OFF_FF2 (OFF_FF1 + 4*2048*512)
#define OFF_XM1 (OFF_FF2 + 4*512*2048)
#define OFF_ME2 (OFF_XM1 + 512*512)
#define WT_TOTAL (OFF_ME2 + 512*512)
__device__ __nv_bfloat16 g_wt[WT_TOTAL];

__device__ __forceinline__ float gelu_exact(float v) {
    return 0.5f * v * (1.0f + erff(v * 0.7071067811865475f));
}

// ---- weight transpose: Wt[n][k] = bf16(W[k][n]) ----
__global__ void wtrans(const float* __restrict__ W, __nv_bfloat16* __restrict__ Wt, int K, int N) {
    __shared__ float t[32][33];
    size_t ws = (size_t)K*N;
    const float* Wl = W + blockIdx.z*ws;
    __nv_bfloat16* Wtl = Wt + blockIdx.z*ws;
    int k0 = blockIdx.x*32, n0 = blockIdx.y*32;
    for (int i = threadIdx.y; i < 32; i += 8)
        t[i][threadIdx.x] = Wl[(size_t)(k0+i)*N + n0 + threadIdx.x];
    __syncthreads();
    for (int i = threadIdx.y; i < 32; i += 8)
        Wtl[(size_t)(n0+i)*K + k0 + threadIdx.x] = __float2bfloat16(t[threadIdx.x][i]);
}

// ---- embed (dual write) ----
__global__ void embed_kernel(const float* __restrict__ u, const float* __restrict__ y,
                             const float* __restrict__ W_in, const float* __restrict__ b_in,
                             float* __restrict__ x, __nv_bfloat16* __restrict__ x16) {
    int n = blockIdx.x, c = threadIdx.x;
    int b = n >> 11, t = n & (SEQ - 1);
    __shared__ float ua[24];
    if (c < 8)       ua[c] = u[(size_t)(b*8 + c)*SEQ + t];
    else if (c < 16) ua[c] = 0.0f;
    else if (c < 24) ua[c] = (t < KTRUE) ? y[(size_t)(b*8 + (c-16))*SEQ + t] : 0.0f;
    __syncthreads();
    float s = b_in[c];
    #pragma unroll
    for (int k = 0; k < 24; k++) s = fmaf(ua[k], W_in[k*HID + c], s);
    float div = __expf(-9.210340371976184f * (float)(c & ~1) / (float)HID);
    float ang = (float)t * div;
    s += (c & 1) ? cosf(ang) : sinf(ang);
    x[(size_t)n*HID + c] = s;
    x16[(size_t)n*HID + c] = __float2bfloat16(s);
}

// ---- WMMA bf16 GEMM: C = A[M,K] @ B[N,K]^T + bias (+gelu) ----
// block 128x128, 8 warps as 4x2, warp tile 32x64 (2x4 wmma 16x16x16 frags)
#define WLDA 40
__global__ __launch_bounds__(256) void gemm_wmma(
    const __nv_bfloat16* __restrict__ A, const __nv_bfloat16* __restrict__ B,
    const float* __restrict__ bias, float* __restrict__ C32,
    __nv_bfloat16* __restrict__ C16, int N, int K, int gelu) {
    __shared__ __nv_bfloat16 As[128][WLDA];
    __shared__ __nv_bfloat16 Bs[128][WLDA];
    __shared__ float stage[8][16][16];
    const int tid = threadIdx.x;
    const int wid = tid >> 5, lane = tid & 31;
    const int wm = wid >> 1, wn = wid & 1;
    const int bm = blockIdx.y*128, bn = blockIdx.x*128;

    wmma::fragment<wmma::accumulator,16,16,16,float> c[2][4];
    #pragma unroll
    for (int i = 0; i < 2; i++)
        #pragma unroll
        for (int j = 0; j < 4; j++) wmma::fill_fragment(c[i][j], 0.0f);

    const int lr = tid >> 1, lc = (tid & 1)*16;
    for (int kk = 0; kk < K; kk += 32) {
        // 128 rows x 32 cols bf16: each thread loads 16 bf16 (2 x uint4)
        *(uint4*)&As[lr][lc]     = *(const uint4*)(A + (size_t)(bm+lr)*K + kk + lc);
        *(uint4*)&As[lr][lc+8]   = *(const uint4*)(A + (size_t)(bm+lr)*K + kk + lc + 8);
        *(uint4*)&Bs[lr][lc]     = *(const uint4*)(B + (size_t)(bn+lr)*K + kk + lc);
        *(uint4*)&Bs[lr][lc+8]   = *(const uint4*)(B + (size_t)(bn+lr)*K + kk + lc + 8);
        __syncthreads();
        #pragma unroll
        for (int ks = 0; ks < 2; ks++) {
            wmma::fragment<wmma::matrix_a,16,16,16,__nv_bfloat16,wmma::row_major> af[2];
            wmma::fragment<wmma::matrix_b,16,16,16,__nv_bfloat16,wmma::col_major> bf[4];
            #pragma unroll
            for (int i = 0; i < 2; i++)
                wmma::load_matrix_sync(af[i], &As[wm*32 + i*16][ks*16], WLDA);
            #pragma unroll
            for (int j = 0; j < 4; j++)
                wmma::load_matrix_sync(bf[j], &Bs[wn*64 + j*16][ks*16], WLDA);
            #pragma unroll
            for (int i = 0; i < 2; i++)
                #pragma unroll
                for (int j = 0; j < 4; j++)
                    wmma::mma_sync(c[i][j], af[i], bf[j], c[i][j]);
        }
        __syncthreads();
    }
    // epilogue: per-warp staging, bias + optional gelu
    #pragma unroll
    for (int i = 0; i < 2; i++) {
        #pragma unroll
        for (int j = 0; j < 4; j++) {
            wmma::store_matrix_sync(&stage[wid][0][0], c[i][j], 16, wmma::mem_row_major);
            __syncwarp();
            #pragma unroll
            for (int e = 0; e < 8; e++) {
                int idx = lane + e*32;
                int r = idx >> 4, cc = idx & 15;
                int grow = bm + wm*32 + i*16 + r;
                int gcol = bn + wn*64 + j*16 + cc;
                float v = stage[wid][r][cc] + bias[gcol];
                if (gelu) v = gelu_exact(v);
                if (C32) C32[(size_t)grow*N + gcol] = v;
                if (C16) C16[(size_t)grow*N + gcol] = __float2bfloat16(v);
            }
            __syncwarp();
        }
    }
}

// ---- naive fp32 gemm for tiny head shapes ----
__global__ void gemm_naive(const float* __restrict__ A, const float* __restrict__ W,
                           const float* __restrict__ bias, float* __restrict__ Cf,
                           __nv_bfloat16* __restrict__ Cb, int N, int K, int gelu) {
    int idx = blockIdx.x*256 + threadIdx.x;
    int row = idx / N, col = idx - row*N;
    float s = bias[col];
    const float* a = A + (size_t)row*K;
    for (int k = 0; k < K; k++) s = fmaf(a[k], W[(size_t)k*N + col], s);
    if (gelu) s = gelu_exact(s);
    if (Cf) Cf[idx] = s;
    if (Cb) Cb[idx] = __float2bfloat16(s);
}

// ---- flash v2: QT=64, KC=64, register softmax, bf16 V, bf16 out ----
#define QT 64
#define KC 64
#define QPAD 132
#define KPAD 132
#define SPAD 68
#define F2_Q  0
#define F2_K  8448
#define F2_S  (8448+8448)
#define F2_RM (F2_S+4352)
#define F2_RL (F2_RM+64)
#define F2_RS (F2_RL+64)
#define F2_V  (F2_RS+64)
// V tile: 64 rows x 128 bf16 = 8192 bf16 = 16384 bytes = 4096 float slots
#define FLASH2_SMEM ((F2_V + 4096)*4)
extern __shared__ char dynsm[];

__global__ __launch_bounds__(256, 2) void flash2(const float* __restrict__ qkv,
                                                 __nv_bfloat16* __restrict__ out16) {
    float* sm = (float*)dynsm;
    float* Qs = sm + F2_Q; float* Ks = sm + F2_K; float* Ss = sm + F2_S;
    float* rm = sm + F2_RM; float* rl = sm + F2_RL; float* rs = sm + F2_RS;
    __nv_bfloat16* Vs = (__nv_bfloat16*)(sm + F2_V);

    const int tid = threadIdx.x;
    const int n0 = blockIdx.x * QT, hh = blockIdx.y;
    const int t0 = n0 & (SEQ - 1), bb = n0 >> 11;
    {
        int r = tid >> 2, c4 = (tid & 3) * 32;
        const float* qp = qkv + (size_t)(n0 + r)*(3*HID) + hh*DHEAD + c4;
        float* qd = &Qs[r*QPAD + c4];
        #pragma unroll
        for (int q = 0; q < 8; q++) *(float4*)(qd + q*4) = *(const float4*)(qp + q*4);
    }
    if (tid < QT) { rm[tid] = -1e30f; rl[tid] = 0.0f; rs[tid] = 1.0f; }

    float acc[8][4];
    #pragma unroll
    for (int i = 0; i < 8; i++) { acc[i][0]=0; acc[i][1]=0; acc[i][2]=0; acc[i][3]=0; }

    const int rgs = tid >> 4, cgs = tid & 15;
    const int wrow = (tid >> 5) * 8, dcol = (tid & 31) * 4;
    int jstart = t0 - (WINDOW - 1); if (jstart < 0) jstart = 0;
    const int tmax = t0 + QT - 1;
    __syncthreads();

    for (int jc = jstart; jc <= tmax; jc += KC) {
        {
            int r = tid >> 2, c4 = (tid & 3) * 32;
            int ja = jc + r; if (ja > tmax) ja = tmax;
            const float* kp = qkv + (size_t)((bb << 11) + ja)*(3*HID) + HID + hh*DHEAD + c4;
            const float* vp = kp + HID;
            float* kd = &Ks[r*KPAD + c4];
            __nv_bfloat16* vd = &Vs[r*DHEAD + c4];
            #pragma unroll
            for (int q = 0; q < 8; q++) {
                *(float4*)(kd + q*4) = *(const float4*)(kp + q*4);
                float4 v = *(const float4*)(vp + q*4);
                __nv_bfloat162 p0, p1;
                p0.x = __float2bfloat16(v.x); p0.y = __float2bfloat16(v.y);
                p1.x = __float2bfloat16(v.z); p1.y = __float2bfloat16(v.w);
                *(__nv_bfloat162*)(vd + q*4) = p0;
                *(__nv_bfloat162*)(vd + q*4 + 2) = p1;
            }
        }
        __syncthreads();

        float s[4][4];
        #pragma unroll
        for (int i = 0; i < 4; i++) { s[i][0]=0; s[i][1]=0; s[i][2]=0; s[i][3]=0; }
        #pragma unroll 8
        for (int k = 0; k < DHEAD; k += 4) {
            float4 kv[4], qv[4];
            #pragma unroll
            for (int j = 0; j < 4; j++) kv[j] = *(float4*)&Ks[(cgs*4 + j)*KPAD + k];
            #pragma unroll
            for (int i = 0; i < 4; i++) qv[i] = *(float4*)&Qs[(rgs*4 + i)*QPAD + k];
            #pragma unroll
            for (int i = 0; i < 4; i++)
                #pragma unroll
                for (int j = 0; j < 4; j++) {
                    s[i][j] = fmaf(qv[i].x, kv[j].x, s[i][j]);
                    s[i][j] = fmaf(qv[i].y, kv[j].y, s[i][j]);
                    s[i][j] = fmaf(qv[i].z, kv[j].z, s[i][j]);
                    s[i][j] = fmaf(qv[i].w, kv[j].w, s[i][j]);
                }
        }
        #pragma unroll
        for (int i = 0; i < 4; i++) {
            int tr = t0 + rgs*4 + i;
            float sv[4], mrow = -1e30f;
            #pragma unroll
            for (int j = 0; j < 4; j++) {
                int ja = jc + cgs*4 + j;
                bool ok = (ja <= tr) && (ja > tr - WINDOW);
                sv[j] = ok ? s[i][j] * 0.08838834764831845f : -1e30f;
                mrow = fmaxf(mrow, sv[j]);
            }
            #pragma unroll
            for (int o = 1; o < 16; o <<= 1)
                mrow = fmaxf(mrow, __shfl_xor_sync(0xffffffffu, mrow, o));
            float mprev = rm[rgs*4 + i];
            float mc = fmaxf(mprev, mrow);
            float lrow = 0.0f;
            #pragma unroll
            for (int j = 0; j < 4; j++) {
                float p = (sv[j] <= -1e29f) ? 0.0f : __expf(sv[j] - mc);
                sv[j] = p; lrow += p;
            }
            #pragma unroll
            for (int o = 1; o < 16; o <<= 1)
                lrow += __shfl_xor_sync(0xffffffffu, lrow, o);
            if (cgs == 0) {
                float sc = __expf(mprev - mc);
                rs[rgs*4 + i] = sc;
                rl[rgs*4 + i] = rl[rgs*4 + i] * sc + lrow;
                rm[rgs*4 + i] = mc;
            }
            float4 pf = {sv[0], sv[1], sv[2], sv[3]};
            *(float4*)&Ss[(rgs*4 + i)*SPAD + cgs*4] = pf;
        }
        __syncthreads();

        #pragma unroll
        for (int i = 0; i < 8; i++) {
            float sc = rs[wrow + i];
            acc[i][0] *= sc; acc[i][1] *= sc; acc[i][2] *= sc; acc[i][3] *= sc;
        }
        #pragma unroll 4
        for (int jg = 0; jg < 16; jg++) {
            float v[4][4];
            #pragma unroll
            for (int jj = 0; jj < 4; jj++) {
                uint2 raw = *(uint2*)&Vs[(jg*4 + jj)*DHEAD + dcol];
                __nv_bfloat162 b0 = *(__nv_bfloat162*)&raw.x;
                __nv_bfloat162 b1 = *(__nv_bfloat162*)&raw.y;
                v[jj][0] = __bfloat162float(b0.x); v[jj][1] = __bfloat162float(b0.y);
                v[jj][2] = __bfloat162float(b1.x); v[jj][3] = __bfloat162float(b1.y);
            }
            #pragma unroll
            for (int i = 0; i < 8; i++) {
                float4 p4 = *(float4*)&Ss[(wrow + i)*SPAD + jg*4];
                #pragma unroll
                for (int d = 0; d < 4; d++) {
                    acc[i][d] = fmaf(p4.x, v[0][d], acc[i][d]);
                    acc[i][d] = fmaf(p4.y, v[1][d], acc[i][d]);
                    acc[i][d] = fmaf(p4.z, v[2][d], acc[i][d]);
                    acc[i][d] = fmaf(p4.w, v[3][d], acc[i][d]);
                }
            }
        }
        __syncthreads();
    }
    #pragma unroll
    for (int i = 0; i < 8; i++) {
        float inv = 1.0f / rl[wrow + i];
        __nv_bfloat162 o0, o1;
        o0.x = __float2bfloat16(acc[i][0]*inv); o0.y = __float2bfloat16(acc[i][1]*inv);
        o1.x = __float2bfloat16(acc[i][2]*inv); o1.y = __float2bfloat16(acc[i][3]*inv);
        __nv_bfloat16* op = out16 + (size_t)(n0 + wrow + i)*HID + hh*DHEAD + dcol;
        *(__nv_bfloat162*)op = o0;
        *(__nv_bfloat162*)(op + 2) = o1;
    }
}

// ---- residual + LayerNorm (dual write) ----
__global__ __launch_bounds__(256) void ln_kernel(float* __restrict__ x,
                                                 const float* __restrict__ add,
                                                 const float* __restrict__ g,
                                                 const float* __restrict__ b,
                                                 __nv_bfloat16* __restrict__ x16) {
    const int n = blockIdx.x, tid = threadIdx.x;
    const int c0 = tid, c1 = tid + 256;
    float v0 = x[(size_t)n*HID + c0];
    float v1 = x[(size_t)n*HID + c1];
    if (add) { v0 += add[(size_t)n*HID + c0]; v1 += add[(size_t)n*HID + c1]; }
    float s = v0 + v1, sq = v0*v0 + v1*v1;
    #pragma unroll
    for (int o = 16; o > 0; o >>= 1) {
        s  += __shfl_xor_sync(0xffffffffu, s,  o);
        sq += __shfl_xor_sync(0xffffffffu, sq, o);
    }
    __shared__ float ss[8], qq[8], shm, shr;
    int w = tid >> 5;
    if ((tid & 31) == 0) { ss[w] = s; qq[w] = sq; }
    __syncthreads();
    if (tid == 0) {
        float S = 0, Q = 0;
        #pragma unroll
        for (int i = 0; i < 8; i++) { S += ss[i]; Q += qq[i]; }
        float mean = S * (1.0f/512.0f);
        shm = mean;
        shr = rsqrtf(Q * (1.0f/512.0f) - mean*mean + LN_EPS);
    }
    __syncthreads();
    float mean = shm, rstd = shr;
    float o0 = (v0 - mean) * rstd * g[c0] + b[c0];
    float o1 = (v1 - mean) * rstd * g[c1] + b[c1];
    x[(size_t)n*HID + c0] = o0;
    x[(size_t)n*HID + c1] = o1;
    x16[(size_t)n*HID + c0] = __float2bfloat16(o0);
    x16[(size_t)n*HID + c1] = __float2bfloat16(o1);
}

// ---- loss ----
__global__ __launch_bounds__(1024) void loss_kernel(const float* __restrict__ yhat,
                                                    const float* __restrict__ y,
                                                    float* __restrict__ out) {
    float s = 0.0f;
    for (int e = threadIdx.x; e < NTOK*8; e += 1024) {
        int n = e >> 3, d = e & 7;
        int b = n >> 11, t = n & (SEQ - 1);
        float diff = yhat[e] - y[(size_t)(b*8 + d)*SEQ + t];
        s = fmaf(diff, diff, s);
    }
    #pragma unroll
    for (int o = 16; o > 0; o >>= 1) s += __shfl_xor_sync(0xffffffffu, s, o);
    __shared__ float red[32];
    int w = threadIdx.x >> 5;
    if ((threadIdx.x & 31) == 0) red[w] = s;
    __syncthreads();
    if (threadIdx.x == 0) {
        float tot = 0;
        #pragma unroll
        for (int i = 0; i < 32; i++) tot += red[i];
        out[0] = tot;
    }
}

// ---- host ----
static inline void run_wm(const __nv_bfloat16* A, const __nv_bfloat16* B, const float* bias,
                          float* C32, __nv_bfloat16* C16, int N, int K, int gelu) {
    gemm_wmma<<<dim3(N/128, NTOK/128), 256>>>(A, B, bias, C32, C16, N, K, gelu);
}

extern "C" void kernel_launch(void* const* d_in, const int* in_sizes, int n_in,
                              void* d_out, int out_size) {
    const float *u = (const float*)d_in[0], *y = (const float*)d_in[1];
    const float *W_in = (const float*)d_in[2], *b_in = (const float*)d_in[3];
    const float *qkv_w = (const float*)d_in[4], *qkv_b = (const float*)d_in[5];
    const float *out_w = (const float*)d_in[6], *out_b = (const float*)d_in[7];
    const float *ff1_w = (const float*)d_in[8], *ff1_b = (const float*)d_in[9];
    const float *ff2_w = (const float*)d_in[10], *ff2_b = (const float*)d_in[11];
    const float *ln1_g = (const float*)d_in[12], *ln1_b = (const float*)d_in[13];
    const float *ln2_g = (const float*)d_in[14], *ln2_b = (const float*)d_in[15];
    const float *lnf_g = (const float*)d_in[16], *lnf_b = (const float*)d_in[17];
    const float *xm1_w = (const float*)d_in[18], *xm1_b = (const float*)d_in[19];
    const float *xm2_w = (const float*)d_in[20], *xm2_b = (const float*)d_in[21];
    const float *me1_w = (const float*)d_in[22], *me1_b = (const float*)d_in[23];
    const float *me2_w = (const float*)d_in[24], *me2_b = (const float*)d_in[25];
    const float *me3_w = (const float*)d_in[26], *me3_b = (const float*)d_in[27];

    static float *px = nullptr, *pqkv, *pt2, *psmall, *pyhat;
    static __nv_bfloat16 *px16, *pattn16, *pmid16, *pwt;
    if (!px) {
        cudaGetSymbolAddress((void**)&px, g_x);
        cudaGetSymbolAddress((void**)&pqkv, g_qkv);
        cudaGetSymbolAddress((void**)&pt2, g_t2);
        cudaGetSymbolAddress((void**)&psmall, g_small);
        cudaGetSymbolAddress((void**)&pyhat, g_yhat);
        cudaGetSymbolAddress((void**)&px16, g_x16);
        cudaGetSymbolAddress((void**)&pattn16, g_attn16);
        cudaGetSymbolAddress((void**)&pmid16, g_mid16);
        cudaGetSymbolAddress((void**)&pwt, g_wt);
        cudaFuncSetAttribute(flash2, cudaFuncAttributeMaxDynamicSharedMemorySize, FLASH2_SMEM);
    }

    dim3 tb(32, 8);
    wtrans<<<dim3(16, 48, 4), tb>>>(qkv_w, pwt + OFF_QKV, 512, 1536);
    wtrans<<<dim3(16, 16, 4), tb>>>(out_w, pwt + OFF_OUT, 512, 512);
    wtrans<<<dim3(16, 64, 4), tb>>>(ff1_w, pwt + OFF_FF1, 512, 2048);
    wtrans<<<dim3(64, 16, 4), tb>>>(ff2_w, pwt + OFF_FF2, 2048, 512);
    wtrans<<<dim3(16, 16, 1), tb>>>(xm1_w, pwt + OFF_XM1, 512, 512);
    wtrans<<<dim3(16, 16, 1), tb>>>(me2_w, pwt + OFF_ME2, 512, 512);

    embed_kernel<<<NTOK, HID>>>(u, y, W_in, b_in, px, px16);

    for (int l = 0; l < NLAYER; l++) {
        run_wm(px16, pwt + OFF_QKV + (size_t)l*1536*512, qkv_b + l*1536, pqkv, nullptr, 1536, 512, 0);
        flash2<<<dim3(NTOK/QT, NHEAD), 256, FLASH2_SMEM>>>(pqkv, pattn16);
        run_wm(pattn16, pwt + OFF_OUT + (size_t)l*512*512, out_b + l*512, pt2, nullptr, 512, 512, 0);
        ln_kernel<<<NTOK, 256>>>(px, pt2, ln1_g + l*HID, ln1_b + l*HID, px16);
        run_wm(px16, pwt + OFF_FF1 + (size_t)l*512*2048, ff1_b + l*2048, nullptr, pmid16, 2048, 512, 1);
        run_wm(pmid16, pwt + OFF_FF2 + (size_t)l*2048*512, ff2_b + l*512, pt2, nullptr, 512, 2048, 0);
        ln_kernel<<<NTOK, 256>>>(px, pt2, ln2_g + l*HID, ln2_b + l*HID, px16);
    }
    ln_kernel<<<NTOK, 256>>>(px, nullptr, lnf_g, lnf_b, px16);

    run_wm(px16, pwt + OFF_XM1, xm1_b, pt2, nullptr, 512, 512, 1);           // gelu(x@xm1)
    gemm_naive<<<NTOK*16/256, 256>>>(pt2, xm2_w, xm2_b, psmall, nullptr, 16, 512, 0);
    gemm_naive<<<NTOK*512/256, 256>>>(psmall, me1_w, me1_b, nullptr, pattn16, 512, 16, 1);
    run_wm(pattn16, pwt + OFF_ME2, me2_b, pqkv, nullptr, 512, 512, 1);       // gelu
    gemm_naive<<<NTOK*8/256, 256>>>(pqkv, me3_w, me3_b, pyhat, nullptr, 8, 512, 0);

    loss_kernel<<<1, 1024>>>(pyhat, y, (float*)d_out);
}

// round 7
// speedup vs baseline: 2.6601x; 1.4165x over previous
#include <cuda_runtime.h>
#include <cuda_bf16.h>
#include <mma.h>
#include <math.h>
#include <stdint.h>

using namespace nvcuda;

#define BATCH 4
#define SEQ   2048
#define HID   512
#define DFF   2048
#define NLAYER 4
#define NHEAD 4
#define DHEAD 128
#define WINDOW 606
#define KTRUE 30
#define NTOK  (BATCH*SEQ)
#define LN_EPS 1e-5f

// ---- scratch ----
__device__ float g_x[NTOK*HID];
__device__ float g_qkv[NTOK*3*HID];      // reused as generic fp32 buffer
__device__ float g_t2[NTOK*HID];
__device__ float g_small[NTOK*16];
__device__ float g_yhat[NTOK*8];
__device__ __nv_bfloat16 g_qkv16[NTOK*3*HID];
__device__ __nv_bfloat16 g_x16[NTOK*HID];
__device__ __nv_bfloat16 g_attn16[NTOK*HID];
__device__ __nv_bfloat16 g_mid16[NTOK*DFF];
// transposed bf16 weights [N,K]
#define OFF_QKV 0
#define OFF_OUT (OFF_QKV + 4*1536*512)
#define OFF_FF1 (OFF_OUT + 4*512*512)
#define OFF_FF2 (OFF_FF1 + 4*2048*512)
#define OFF_XM1 (OFF_FF2 + 4*512*2048)
#define OFF_ME2 (OFF_XM1 + 512*512)
#define WT_TOTAL (OFF_ME2 + 512*512)
__device__ __nv_bfloat16 g_wt[WT_TOTAL];

__device__ __forceinline__ float gelu_exact(float v) {
    return 0.5f * v * (1.0f + erff(v * 0.7071067811865475f));
}
__device__ __forceinline__ uint32_t smem_u32(const void* p) {
    uint32_t a;
    asm("{ .reg .u64 t; cvta.to.shared.u64 t, %1; cvt.u32.u64 %0, t; }" : "=r"(a) : "l"(p));
    return a;
}
__device__ __forceinline__ void cp16(uint32_t d, const void* s) {
    asm volatile("cp.async.cg.shared.global [%0], [%1], 16;" :: "r"(d), "l"(s));
}
#define CP_COMMIT() asm volatile("cp.async.commit_group;" ::: "memory")
#define CP_WAIT1()  asm volatile("cp.async.wait_group 1;" ::: "memory")
#define CP_WAIT0()  asm volatile("cp.async.wait_group 0;" ::: "memory")

__device__ __forceinline__ void bf4_to_f4(const __nv_bfloat16* p, float* o) {
    uint2 raw = *(const uint2*)p;
    __nv_bfloat162 a = *(__nv_bfloat162*)&raw.x;
    __nv_bfloat162 b = *(__nv_bfloat162*)&raw.y;
    float2 fa = __bfloat1622float2(a), fb = __bfloat1622float2(b);
    o[0] = fa.x; o[1] = fa.y; o[2] = fb.x; o[3] = fb.y;
}

extern __shared__ char dynsm[];

// ---- weight transpose: Wt[n][k] = bf16(W[k][n]) ----
__global__ void wtrans(const float* __restrict__ W, __nv_bfloat16* __restrict__ Wt, int K, int N) {
    __shared__ float t[32][33];
    size_t ws = (size_t)K*N;
    const float* Wl = W + blockIdx.z*ws;
    __nv_bfloat16* Wtl = Wt + blockIdx.z*ws;
    int k0 = blockIdx.x*32, n0 = blockIdx.y*32;
    for (int i = threadIdx.y; i < 32; i += 8)
        t[i][threadIdx.x] = Wl[(size_t)(k0+i)*N + n0 + threadIdx.x];
    __syncthreads();
    for (int i = threadIdx.y; i < 32; i += 8)
        Wtl[(size_t)(n0+i)*K + k0 + threadIdx.x] = __float2bfloat16(t[threadIdx.x][i]);
}

// ---- embed (dual write) ----
__global__ void embed_kernel(const float* __restrict__ u, const float* __restrict__ y,
                             const float* __restrict__ W_in, const float* __restrict__ b_in,
                             float* __restrict__ x, __nv_bfloat16* __restrict__ x16) {
    int n = blockIdx.x, c = threadIdx.x;
    int b = n >> 11, t = n & (SEQ - 1);
    __shared__ float ua[24];
    if (c < 8)       ua[c] = u[(size_t)(b*8 + c)*SEQ + t];
    else if (c < 16) ua[c] = 0.0f;
    else if (c < 24) ua[c] = (t < KTRUE) ? y[(size_t)(b*8 + (c-16))*SEQ + t] : 0.0f;
    __syncthreads();
    float s = b_in[c];
    #pragma unroll
    for (int k = 0; k < 24; k++) s = fmaf(ua[k], W_in[k*HID + c], s);
    float div = __expf(-9.210340371976184f * (float)(c & ~1) / (float)HID);
    float ang = (float)t * div;
    s += (c & 1) ? cosf(ang) : sinf(ang);
    x[(size_t)n*HID + c] = s;
    x16[(size_t)n*HID + c] = __float2bfloat16(s);
}

// ---- WMMA bf16 GEMM, cp.async double-buffered: C = A[M,K] @ B[N,K]^T + bias (+gelu) ----
// block 128x128, 8 warps 4x2, warp tile 32x64; K-chunks of 64, ldm=72
#define TK 64
#define WLD 72
#define ABUF_B 18432                     // 128*72*2 bytes per buffer
#define GEMM_SMEM (4*ABUF_B + 8192)      // As[2] + Bs[2] + stage
__global__ __launch_bounds__(256) void gemm_wmma(
    const __nv_bfloat16* __restrict__ A, const __nv_bfloat16* __restrict__ B,
    const float* __restrict__ bias, float* __restrict__ C32,
    __nv_bfloat16* __restrict__ C16, int N, int K, int gelu) {
    const int tid = threadIdx.x;
    const int wid = tid >> 5, lane = tid & 31;
    const int wm = wid >> 1, wn = wid & 1;
    const int bm = blockIdx.y*128, bn = blockIdx.x*128;
    const uint32_t sbase = smem_u32(dynsm);
    float* stage = (float*)(dynsm + 4*ABUF_B);

    wmma::fragment<wmma::accumulator,16,16,16,float> c[2][4];
    #pragma unroll
    for (int i = 0; i < 2; i++)
        #pragma unroll
        for (int j = 0; j < 4; j++) wmma::fill_fragment(c[i][j], 0.0f);

    const int lr = tid >> 1, lc0 = (tid & 1)*32;
    const int nch = K / TK;
    const __nv_bfloat16* gA = A + (size_t)(bm+lr)*K + lc0;
    const __nv_bfloat16* gB = B + (size_t)(bn+lr)*K + lc0;
    const uint32_t soff = (uint32_t)(lr*WLD + lc0)*2;

    // prologue
    {
        uint32_t ua = sbase + soff, ub = sbase + 2*ABUF_B + soff;
        #pragma unroll
        for (int q = 0; q < 4; q++) {
            cp16(ua + q*16, gA + q*8);
            cp16(ub + q*16, gB + q*8);
        }
        CP_COMMIT();
    }
    for (int ch = 0; ch < nch; ch++) {
        if (ch + 1 < nch) {
            int buf = (ch + 1) & 1;
            uint32_t ua = sbase + buf*ABUF_B + soff;
            uint32_t ub = sbase + 2*ABUF_B + buf*ABUF_B + soff;
            const __nv_bfloat16* pa = gA + (ch+1)*TK;
            const __nv_bfloat16* pb = gB + (ch+1)*TK;
            #pragma unroll
            for (int q = 0; q < 4; q++) {
                cp16(ua + q*16, pa + q*8);
                cp16(ub + q*16, pb + q*8);
            }
            CP_COMMIT();
            CP_WAIT1();
        } else {
            CP_WAIT0();
        }
        __syncthreads();
        const __nv_bfloat16* Asb = (const __nv_bfloat16*)(dynsm + (ch&1)*ABUF_B);
        const __nv_bfloat16* Bsb = (const __nv_bfloat16*)(dynsm + 2*ABUF_B + (ch&1)*ABUF_B);
        #pragma unroll
        for (int ks = 0; ks < 4; ks++) {
            wmma::fragment<wmma::matrix_a,16,16,16,__nv_bfloat16,wmma::row_major> af[2];
            wmma::fragment<wmma::matrix_b,16,16,16,__nv_bfloat16,wmma::col_major> bf[4];
            #pragma unroll
            for (int i = 0; i < 2; i++)
                wmma::load_matrix_sync(af[i], Asb + (wm*32 + i*16)*WLD + ks*16, WLD);
            #pragma unroll
            for (int j = 0; j < 4; j++)
                wmma::load_matrix_sync(bf[j], Bsb + (wn*64 + j*16)*WLD + ks*16, WLD);
            #pragma unroll
            for (int i = 0; i < 2; i++)
                #pragma unroll
                for (int j = 0; j < 4; j++)
                    wmma::mma_sync(c[i][j], af[i], bf[j], c[i][j]);
        }
        __syncthreads();
    }
    // epilogue
    #pragma unroll
    for (int i = 0; i < 2; i++) {
        #pragma unroll
        for (int j = 0; j < 4; j++) {
            wmma::store_matrix_sync(stage + wid*256, c[i][j], 16, wmma::mem_row_major);
            __syncwarp();
            #pragma unroll
            for (int e = 0; e < 8; e++) {
                int idx = lane + e*32;
                int r = idx >> 4, cc = idx & 15;
                int grow = bm + wm*32 + i*16 + r;
                int gcol = bn + wn*64 + j*16 + cc;
                float v = stage[wid*256 + r*16 + cc] + bias[gcol];
                if (gelu) v = gelu_exact(v);
                if (C32) C32[(size_t)grow*N + gcol] = v;
                if (C16) C16[(size_t)grow*N + gcol] = __float2bfloat16(v);
            }
            __syncwarp();
        }
    }
}

// ---- naive fp32 gemm for tiny head shapes ----
__global__ void gemm_naive(const float* __restrict__ A, const float* __restrict__ W,
                           const float* __restrict__ bias, float* __restrict__ Cf,
                           __nv_bfloat16* __restrict__ Cb, int N, int K, int gelu) {
    int idx = blockIdx.x*256 + threadIdx.x;
    int row = idx / N, col = idx - row*N;
    float s = bias[col];
    const float* a = A + (size_t)row*K;
    for (int k = 0; k < K; k++) s = fmaf(a[k], W[(size_t)k*N + col], s);
    if (gelu) s = gelu_exact(s);
    if (Cf) Cf[idx] = s;
    if (Cb) Cb[idx] = __float2bfloat16(s);
}

// ---- flash v3: bf16 qkv, QT=64, KC=64, register softmax ----
#define QT 64
#define KC 64
#define QKP 132                  // bf16 row stride for Q/K (264 B: conflict-free)
#define SPAD 68
// byte offsets
#define F3_Q  0
#define F3_K  16896
#define F3_V  33792
#define F3_S  50176
#define F3_RM 67584
#define FLASH3_SMEM (F3_RM + 768)

__global__ __launch_bounds__(256) void flash3(const __nv_bfloat16* __restrict__ qkv,
                                              __nv_bfloat16* __restrict__ out16) {
    __nv_bfloat16* Qs = (__nv_bfloat16*)dynsm;
    __nv_bfloat16* Ks = (__nv_bfloat16*)(dynsm + F3_K);
    __nv_bfloat16* Vs = (__nv_bfloat16*)(dynsm + F3_V);
    float* Ss = (float*)(dynsm + F3_S);
    float* rm = (float*)(dynsm + F3_RM);
    float* rl = rm + 64; float* rs = rl + 64;

    const int tid = threadIdx.x;
    const int n0 = blockIdx.x * QT, hh = blockIdx.y;
    const int t0 = n0 & (SEQ - 1), bb = n0 >> 11;
    // Q tile load (bf16, uint2 stores for 8B alignment)
    {
        int r = tid >> 2, c0 = (tid & 3)*32;
        const __nv_bfloat16* qp = qkv + (size_t)(n0 + r)*1536 + hh*DHEAD + c0;
        __nv_bfloat16* qd = Qs + r*QKP + c0;
        #pragma unroll
        for (int q = 0; q < 4; q++) {
            uint4 v = *(const uint4*)(qp + q*8);
            *(uint2*)(qd + q*8)     = make_uint2(v.x, v.y);
            *(uint2*)(qd + q*8 + 4) = make_uint2(v.z, v.w);
        }
    }
    if (tid < QT) { rm[tid] = -1e30f; rl[tid] = 0.0f; rs[tid] = 1.0f; }

    float acc[8][4];
    #pragma unroll
    for (int i = 0; i < 8; i++) { acc[i][0]=0; acc[i][1]=0; acc[i][2]=0; acc[i][3]=0; }

    const int rgs = tid >> 4, cgs = tid & 15;       // score: rows rgs*4+i, keys cgs + j*16
    const int wrow = (tid >> 5) * 8, dcol = (tid & 31) * 4;
    int jstart = t0 - (WINDOW - 1); if (jstart < 0) jstart = 0;
    const int tmax = t0 + QT - 1;
    __syncthreads();

    for (int jc = jstart; jc <= tmax; jc += KC) {
        {
            int r = tid >> 2, c0 = (tid & 3)*32;
            int ja = jc + r; if (ja > tmax) ja = tmax;
            const __nv_bfloat16* kp = qkv + (size_t)((bb << 11) + ja)*1536 + HID + hh*DHEAD + c0;
            const __nv_bfloat16* vp = kp + HID;
            __nv_bfloat16* kd = Ks + r*QKP + c0;
            __nv_bfloat16* vd = Vs + r*DHEAD + c0;
            #pragma unroll
            for (int q = 0; q < 4; q++) {
                uint4 kv4 = *(const uint4*)(kp + q*8);
                *(uint2*)(kd + q*8)     = make_uint2(kv4.x, kv4.y);
                *(uint2*)(kd + q*8 + 4) = make_uint2(kv4.z, kv4.w);
                *(uint4*)(vd + q*8) = *(const uint4*)(vp + q*8);
            }
        }
        __syncthreads();

        // scores: 4 rows x 4 keys per thread, bf16 smem
        float s[4][4];
        #pragma unroll
        for (int i = 0; i < 4; i++) { s[i][0]=0; s[i][1]=0; s[i][2]=0; s[i][3]=0; }
        #pragma unroll 4
        for (int k = 0; k < DHEAD; k += 4) {
            float kf[4][4], qf[4][4];
            #pragma unroll
            for (int j = 0; j < 4; j++) bf4_to_f4(Ks + (cgs + j*16)*QKP + k, kf[j]);
            #pragma unroll
            for (int i = 0; i < 4; i++) bf4_to_f4(Qs + (rgs*4 + i)*QKP + k, qf[i]);
            #pragma unroll
            for (int i = 0; i < 4; i++)
                #pragma unroll
                for (int j = 0; j < 4; j++) {
                    s[i][j] = fmaf(qf[i][0], kf[j][0], s[i][j]);
                    s[i][j] = fmaf(qf[i][1], kf[j][1], s[i][j]);
                    s[i][j] = fmaf(qf[i][2], kf[j][2], s[i][j]);
                    s[i][j] = fmaf(qf[i][3], kf[j][3], s[i][j]);
                }
        }
        #pragma unroll
        for (int i = 0; i < 4; i++) {
            int tr = t0 + rgs*4 + i;
            float sv[4], mrow = -1e30f;
            #pragma unroll
            for (int j = 0; j < 4; j++) {
                int ja = jc + cgs + j*16;
                bool ok = (ja <= tr) && (ja > tr - WINDOW);
                sv[j] = ok ? s[i][j] * 0.08838834764831845f : -1e30f;
                mrow = fmaxf(mrow, sv[j]);
            }
            #pragma unroll
            for (int o = 1; o < 16; o <<= 1)
                mrow = fmaxf(mrow, __shfl_xor_sync(0xffffffffu, mrow, o));
            float mprev = rm[rgs*4 + i];
            float mc = fmaxf(mprev, mrow);
            float lrow = 0.0f;
            #pragma unroll
            for (int j = 0; j < 4; j++) {
                float p = (sv[j] <= -1e29f) ? 0.0f : __expf(sv[j] - mc);
                sv[j] = p; lrow += p;
            }
            #pragma unroll
            for (int o = 1; o < 16; o <<= 1)
                lrow += __shfl_xor_sync(0xffffffffu, lrow, o);
            if (cgs == 0) {
                float sc = __expf(mprev - mc);
                rs[rgs*4 + i] = sc;
                rl[rgs*4 + i] = rl[rgs*4 + i] * sc + lrow;
                rm[rgs*4 + i] = mc;
            }
            #pragma unroll
            for (int j = 0; j < 4; j++)
                Ss[(rgs*4 + i)*SPAD + cgs + j*16] = sv[j];
        }
        __syncthreads();

        #pragma unroll
        for (int i = 0; i < 8; i++) {
            float sc = rs[wrow + i];
            acc[i][0] *= sc; acc[i][1] *= sc; acc[i][2] *= sc; acc[i][3] *= sc;
        }
        #pragma unroll 4
        for (int jg = 0; jg < 16; jg++) {
            float v[4][4];
            #pragma unroll
            for (int jj = 0; jj < 4; jj++) {
                uint2 raw = *(uint2*)(Vs + (jg*4 + jj)*DHEAD + dcol);
                __nv_bfloat162 b0 = *(__nv_bfloat162*)&raw.x;
                __nv_bfloat162 b1 = *(__nv_bfloat162*)&raw.y;
                v[jj][0] = __bfloat162float(b0.x); v[jj][1] = __bfloat162float(b0.y);
                v[jj][2] = __bfloat162float(b1.x); v[jj][3] = __bfloat162float(b1.y);
            }
            #pragma unroll
            for (int i = 0; i < 8; i++) {
                float4 p4 = *(float4*)&Ss[(wrow + i)*SPAD + jg*4];
                #pragma unroll
                for (int d = 0; d < 4; d++) {
                    acc[i][d] = fmaf(p4.x, v[0][d], acc[i][d]);
                    acc[i][d] = fmaf(p4.y, v[1][d], acc[i][d]);
                    acc[i][d] = fmaf(p4.z, v[2][d], acc[i][d]);
                    acc[i][d] = fmaf(p4.w, v[3][d], acc[i][d]);
                }
            }
        }
        __syncthreads();
    }
    #pragma unroll
    for (int i = 0; i < 8; i++) {
        float inv = 1.0f / rl[wrow + i];
        __nv_bfloat162 o0, o1;
        o0.x = __float2bfloat16(acc[i][0]*inv); o0.y = __float2bfloat16(acc[i][1]*inv);
        o1.x = __float2bfloat16(acc[i][2]*inv); o1.y = __float2bfloat16(acc[i][3]*inv);
        __nv_bfloat16* op = out16 + (size_t)(n0 + wrow + i)*HID + hh*DHEAD + dcol;
        *(__nv_bfloat162*)op = o0;
        *(__nv_bfloat162*)(op + 2) = o1;
    }
}

// ---- residual + LayerNorm (dual write) ----
__global__ __launch_bounds__(256) void ln_kernel(float* __restrict__ x,
                                                 const float* __restrict__ add,
                                                 const float* __restrict__ g,
                                                 const float* __restrict__ b,
                                                 __nv_bfloat16* __restrict__ x16) {
    const int n = blockIdx.x, tid = threadIdx.x;
    const int c0 = tid, c1 = tid + 256;
    float v0 = x[(size_t)n*HID + c0];
    float v1 = x[(size_t)n*HID + c1];
    if (add) { v0 += add[(size_t)n*HID + c0]; v1 += add[(size_t)n*HID + c1]; }
    float s = v0 + v1, sq = v0*v0 + v1*v1;
    #pragma unroll
    for (int o = 16; o > 0; o >>= 1) {
        s  += __shfl_xor_sync(0xffffffffu, s,  o);
        sq += __shfl_xor_sync(0xffffffffu, sq, o);
    }
    __shared__ float ss[8], qq[8], shm, shr;
    int w = tid >> 5;
    if ((tid & 31) == 0) { ss[w] = s; qq[w] = sq; }
    __syncthreads();
    if (tid == 0) {
        float S = 0, Q = 0;
        #pragma unroll
        for (int i = 0; i < 8; i++) { S += ss[i]; Q += qq[i]; }
        float mean = S * (1.0f/512.0f);
        shm = mean;
        shr = rsqrtf(Q * (1.0f/512.0f) - mean*mean + LN_EPS);
    }
    __syncthreads();
    float mean = shm, rstd = shr;
    float o0 = (v0 - mean) * rstd * g[c0] + b[c0];
    float o1 = (v1 - mean) * rstd * g[c1] + b[c1];
    x[(size_t)n*HID + c0] = o0;
    x[(size_t)n*HID + c1] = o1;
    x16[(size_t)n*HID + c0] = __float2bfloat16(o0);
    x16[(size_t)n*HID + c1] = __float2bfloat16(o1);
}

// ---- loss ----
__global__ __launch_bounds__(1024) void loss_kernel(const float* __restrict__ yhat,
                                                    const float* __restrict__ y,
                                                    float* __restrict__ out) {
    float s = 0.0f;
    for (int e = threadIdx.x; e < NTOK*8; e += 1024) {
        int n = e >> 3, d = e & 7;
        int b = n >> 11, t = n & (SEQ - 1);
        float diff = yhat[e] - y[(size_t)(b*8 + d)*SEQ + t];
        s = fmaf(diff, diff, s);
    }
    #pragma unroll
    for (int o = 16; o > 0; o >>= 1) s += __shfl_xor_sync(0xffffffffu, s, o);
    __shared__ float red[32];
    int w = threadIdx.x >> 5;
    if ((threadIdx.x & 31) == 0) red[w] = s;
    __syncthreads();
    if (threadIdx.x == 0) {
        float tot = 0;
        #pragma unroll
        for (int i = 0; i < 32; i++) tot += red[i];
        out[0] = tot;
    }
}

// ---- host ----
static inline void run_wm(const __nv_bfloat16* A, const __nv_bfloat16* B, const float* bias,
                          float* C32, __nv_bfloat16* C16, int N, int K, int gelu) {
    gemm_wmma<<<dim3(N/128, NTOK/128), 256, GEMM_SMEM>>>(A, B, bias, C32, C16, N, K, gelu);
}

extern "C" void kernel_launch(void* const* d_in, const int* in_sizes, int n_in,
                              void* d_out, int out_size) {
    const float *u = (const float*)d_in[0], *y = (const float*)d_in[1];
    const float *W_in = (const float*)d_in[2], *b_in = (const float*)d_in[3];
    const float *qkv_w = (const float*)d_in[4], *qkv_b = (const float*)d_in[5];
    const float *out_w = (const float*)d_in[6], *out_b = (const float*)d_in[7];
    const float *ff1_w = (const float*)d_in[8], *ff1_b = (const float*)d_in[9];
    const float *ff2_w = (const float*)d_in[10], *ff2_b = (const float*)d_in[11];
    const float *ln1_g = (const float*)d_in[12], *ln1_b = (const float*)d_in[13];
    const float *ln2_g = (const float*)d_in[14], *ln2_b = (const float*)d_in[15];
    const float *lnf_g = (const float*)d_in[16], *lnf_b = (const float*)d_in[17];
    const float *xm1_w = (const float*)d_in[18], *xm1_b = (const float*)d_in[19];
    const float *xm2_w = (const float*)d_in[20], *xm2_b = (const float*)d_in[21];
    const float *me1_w = (const float*)d_in[22], *me1_b = (const float*)d_in[23];
    const float *me2_w = (const float*)d_in[24], *me2_b = (const float*)d_in[25];
    const float *me3_w = (const float*)d_in[26], *me3_b = (const float*)d_in[27];

    static float *px = nullptr, *pf32, *pt2, *psmall, *pyhat;
    static __nv_bfloat16 *pqkv16, *px16, *pattn16, *pmid16, *pwt;
    if (!px) {
        cudaGetSymbolAddress((void**)&px, g_x);
        cudaGetSymbolAddress((void**)&pf32, g_qkv);
        cudaGetSymbolAddress((void**)&pt2, g_t2);
        cudaGetSymbolAddress((void**)&psmall, g_small);
        cudaGetSymbolAddress((void**)&pyhat, g_yhat);
        cudaGetSymbolAddress((void**)&pqkv16, g_qkv16);
        cudaGetSymbolAddress((void**)&px16, g_x16);
        cudaGetSymbolAddress((void**)&pattn16, g_attn16);
        cudaGetSymbolAddress((void**)&pmid16, g_mid16);
        cudaGetSymbolAddress((void**)&pwt, g_wt);
        cudaFuncSetAttribute(flash3, cudaFuncAttributeMaxDynamicSharedMemorySize, FLASH3_SMEM);
        cudaFuncSetAttribute(gemm_wmma, cudaFuncAttributeMaxDynamicSharedMemorySize, GEMM_SMEM);
    }

    dim3 tb(32, 8);
    wtrans<<<dim3(16, 48, 4), tb>>>(qkv_w, pwt + OFF_QKV, 512, 1536);
    wtrans<<<dim3(16, 16, 4), tb>>>(out_w, pwt + OFF_OUT, 512, 512);
    wtrans<<<dim3(16, 64, 4), tb>>>(ff1_w, pwt + OFF_FF1, 512, 2048);
    wtrans<<<dim3(64, 16, 4), tb>>>(ff2_w, pwt + OFF_FF2, 2048, 512);
    wtrans<<<dim3(16, 16, 1), tb>>>(xm1_w, pwt + OFF_XM1, 512, 512);
    wtrans<<<dim3(16, 16, 1), tb>>>(me2_w, pwt + OFF_ME2, 512, 512);

    embed_kernel<<<NTOK, HID>>>(u, y, W_in, b_in, px, px16);

    for (int l = 0; l < NLAYER; l++) {
        run_wm(px16, pwt + OFF_QKV + (size_t)l*1536*512, qkv_b + l*1536, nullptr, pqkv16, 1536, 512, 0);
        flash3<<<dim3(NTOK/QT, NHEAD), 256, FLASH3_SMEM>>>(pqkv16, pattn16);
        run_wm(pattn16, pwt + OFF_OUT + (size_t)l*512*512, out_b + l*512, pt2, nullptr, 512, 512, 0);
        ln_kernel<<<NTOK, 256>>>(px, pt2, ln1_g + l*HID, ln1_b + l*HID, px16);
        run_wm(px16, pwt + OFF_FF1 + (size_t)l*512*2048, ff1_b + l*2048, nullptr, pmid16, 2048, 512, 1);
        run_wm(pmid16, pwt + OFF_FF2 + (size_t)l*2048*512, ff2_b + l*512, pt2, nullptr, 512, 2048, 0);
        ln_kernel<<<NTOK, 256>>>(px, pt2, ln2_g + l*HID, ln2_b + l*HID, px16);
    }
    ln_kernel<<<NTOK, 256>>>(px, nullptr, lnf_g, lnf_b, px16);

    run_wm(px16, pwt + OFF_XM1, xm1_b, pt2, nullptr, 512, 512, 1);           // gelu(x@xm1)
    gemm_naive<<<NTOK*16/256, 256>>>(pt2, xm2_w, xm2_b, psmall, nullptr, 16, 512, 0);
    gemm_naive<<<NTOK*512/256, 256>>>(psmall, me1_w, me1_b, nullptr, pattn16, 512, 16, 1);
    run_wm(pattn16, pwt + OFF_ME2, me2_b, pf32, nullptr, 512, 512, 1);       // gelu
    gemm_naive<<<NTOK*8/256, 256>>>(pf32, me3_w, me3_b, pyhat, nullptr, 8, 512, 0);

    loss_kernel<<<1, 1024>>>(pyhat, y, (float*)d_out);
}

// round 8
// speedup vs baseline: 4.2078x; 1.5818x over previous
#include <cuda_runtime.h>
#include <cuda_bf16.h>
#include <mma.h>
#include <math.h>
#include <stdint.h>

using namespace nvcuda;

#define BATCH 4
#define SEQ   2048
#define HID   512
#define DFF   2048
#define NLAYER 4
#define NHEAD 4
#define DHEAD 128
#define WINDOW 606
#define KTRUE 30
#define NTOK  (BATCH*SEQ)
#define LN_EPS 1e-5f
#define SM_SCALE 0.08838834764831845f

// ---- scratch ----
__device__ float g_x[NTOK*HID];
__device__ float g_f32[NTOK*3*HID];
__device__ float g_t2[NTOK*HID];
__device__ float g_small[NTOK*16];
__device__ float g_yhat[NTOK*8];
__device__ __nv_bfloat16 g_qkv16[NTOK*3*HID];
__device__ __nv_bfloat16 g_x16[NTOK*HID];
__device__ __nv_bfloat16 g_attn16[NTOK*HID];
__device__ __nv_bfloat16 g_mid16[NTOK*DFF];
#define OFF_QKV 0
#define OFF_OUT (OFF_QKV + 4*1536*512)
#define OFF_FF1 (OFF_OUT + 4*512*512)
#define OFF_FF2 (OFF_FF1 + 4*2048*512)
#define OFF_XM1 (OFF_FF2 + 4*512*2048)
#define OFF_ME2 (OFF_XM1 + 512*512)
#define WT_TOTAL (OFF_ME2 + 512*512)
__device__ __nv_bfloat16 g_wt[WT_TOTAL];

__device__ __forceinline__ float gelu_exact(float v) {
    return 0.5f * v * (1.0f + erff(v * 0.7071067811865475f));
}
__device__ __forceinline__ uint32_t smem_u32(const void* p) {
    uint32_t a;
    asm("{ .reg .u64 t; cvta.to.shared.u64 t, %1; cvt.u32.u64 %0, t; }" : "=r"(a) : "l"(p));
    return a;
}
__device__ __forceinline__ void cp16(uint32_t d, const void* s) {
    asm volatile("cp.async.cg.shared.global [%0], [%1], 16;" :: "r"(d), "l"(s));
}
#define CP_COMMIT() asm volatile("cp.async.commit_group;" ::: "memory")
#define CP_WAIT1()  asm volatile("cp.async.wait_group 1;" ::: "memory")
#define CP_WAIT0()  asm volatile("cp.async.wait_group 0;" ::: "memory")

__device__ __forceinline__ void ldsm_x4(uint32_t& r0, uint32_t& r1, uint32_t& r2, uint32_t& r3,
                                        uint32_t addr) {
    asm volatile("ldmatrix.sync.aligned.m8n8.x4.shared.b16 {%0,%1,%2,%3}, [%4];"
        : "=r"(r0), "=r"(r1), "=r"(r2), "=r"(r3) : "r"(addr));
}
__device__ __forceinline__ void ldsm_x4_t(uint32_t& r0, uint32_t& r1, uint32_t& r2, uint32_t& r3,
                                          uint32_t addr) {
    asm volatile("ldmatrix.sync.aligned.m8n8.x4.trans.shared.b16 {%0,%1,%2,%3}, [%4];"
        : "=r"(r0), "=r"(r1), "=r"(r2), "=r"(r3) : "r"(addr));
}
__device__ __forceinline__ void mma16816(float* d, const uint32_t* a, uint32_t b0, uint32_t b1) {
    asm volatile("mma.sync.aligned.m16n8k16.row.col.f32.bf16.bf16.f32 "
        "{%0,%1,%2,%3}, {%4,%5,%6,%7}, {%8,%9}, {%0,%1,%2,%3};"
        : "+f"(d[0]), "+f"(d[1]), "+f"(d[2]), "+f"(d[3])
        : "r"(a[0]), "r"(a[1]), "r"(a[2]), "r"(a[3]), "r"(b0), "r"(b1));
}
__device__ __forceinline__ uint32_t packbf(float lo, float hi) {
    uint32_t d;
    asm("cvt.rn.bf16x2.f32 %0, %1, %2;" : "=r"(d) : "f"(hi), "f"(lo));
    return d;
}

extern __shared__ char dynsm[];

// ---- weight transpose: Wt[n][k] = bf16(W[k][n]) ----
__global__ void wtrans(const float* __restrict__ W, __nv_bfloat16* __restrict__ Wt, int K, int N) {
    __shared__ float t[32][33];
    size_t ws = (size_t)K*N;
    const float* Wl = W + blockIdx.z*ws;
    __nv_bfloat16* Wtl = Wt + blockIdx.z*ws;
    int k0 = blockIdx.x*32, n0 = blockIdx.y*32;
    for (int i = threadIdx.y; i < 32; i += 8)
        t[i][threadIdx.x] = Wl[(size_t)(k0+i)*N + n0 + threadIdx.x];
    __syncthreads();
    for (int i = threadIdx.y; i < 32; i += 8)
        Wtl[(size_t)(n0+i)*K + k0 + threadIdx.x] = __float2bfloat16(t[threadIdx.x][i]);
}

// ---- embed (dual write) ----
__global__ void embed_kernel(const float* __restrict__ u, const float* __restrict__ y,
                             const float* __restrict__ W_in, const float* __restrict__ b_in,
                             float* __restrict__ x, __nv_bfloat16* __restrict__ x16) {
    int n = blockIdx.x, c = threadIdx.x;
    int b = n >> 11, t = n & (SEQ - 1);
    __shared__ float ua[24];
    if (c < 8)       ua[c] = u[(size_t)(b*8 + c)*SEQ + t];
    else if (c < 16) ua[c] = 0.0f;
    else if (c < 24) ua[c] = (t < KTRUE) ? y[(size_t)(b*8 + (c-16))*SEQ + t] : 0.0f;
    __syncthreads();
    float s = b_in[c];
    #pragma unroll
    for (int k = 0; k < 24; k++) s = fmaf(ua[k], W_in[k*HID + c], s);
    float div = __expf(-9.210340371976184f * (float)(c & ~1) / (float)HID);
    float ang = (float)t * div;
    s += (c & 1) ? cosf(ang) : sinf(ang);
    x[(size_t)n*HID + c] = s;
    x16[(size_t)n*HID + c] = __float2bfloat16(s);
}

// ---- WMMA bf16 GEMM, cp.async double-buffered ----
#define TK 64
#define WLD 72
#define ABUF_B 18432
#define GEMM_SMEM (4*ABUF_B + 8192)
__global__ __launch_bounds__(256) void gemm_wmma(
    const __nv_bfloat16* __restrict__ A, const __nv_bfloat16* __restrict__ B,
    const float* __restrict__ bias, float* __restrict__ C32,
    __nv_bfloat16* __restrict__ C16, int N, int K, int gelu) {
    const int tid = threadIdx.x;
    const int wid = tid >> 5, lane = tid & 31;
    const int wm = wid >> 1, wn = wid & 1;
    const int bm = blockIdx.y*128, bn = blockIdx.x*128;
    const uint32_t sbase = smem_u32(dynsm);
    float* stage = (float*)(dynsm + 4*ABUF_B);

    wmma::fragment<wmma::accumulator,16,16,16,float> c[2][4];
    #pragma unroll
    for (int i = 0; i < 2; i++)
        #pragma unroll
        for (int j = 0; j < 4; j++) wmma::fill_fragment(c[i][j], 0.0f);

    const int lr = tid >> 1, lc0 = (tid & 1)*32;
    const int nch = K / TK;
    const __nv_bfloat16* gA = A + (size_t)(bm+lr)*K + lc0;
    const __nv_bfloat16* gB = B + (size_t)(bn+lr)*K + lc0;
    const uint32_t soff = (uint32_t)(lr*WLD + lc0)*2;

    {
        uint32_t ua = sbase + soff, ub = sbase + 2*ABUF_B + soff;
        #pragma unroll
        for (int q = 0; q < 4; q++) { cp16(ua + q*16, gA + q*8); cp16(ub + q*16, gB + q*8); }
        CP_COMMIT();
    }
    for (int ch = 0; ch < nch; ch++) {
        if (ch + 1 < nch) {
            int buf = (ch + 1) & 1;
            uint32_t ua = sbase + buf*ABUF_B + soff;
            uint32_t ub = sbase + 2*ABUF_B + buf*ABUF_B + soff;
            const __nv_bfloat16* pa = gA + (ch+1)*TK;
            const __nv_bfloat16* pb = gB + (ch+1)*TK;
            #pragma unroll
            for (int q = 0; q < 4; q++) { cp16(ua + q*16, pa + q*8); cp16(ub + q*16, pb + q*8); }
            CP_COMMIT();
            CP_WAIT1();
        } else {
            CP_WAIT0();
        }
        __syncthreads();
        const __nv_bfloat16* Asb = (const __nv_bfloat16*)(dynsm + (ch&1)*ABUF_B);
        const __nv_bfloat16* Bsb = (const __nv_bfloat16*)(dynsm + 2*ABUF_B + (ch&1)*ABUF_B);
        #pragma unroll
        for (int ks = 0; ks < 4; ks++) {
            wmma::fragment<wmma::matrix_a,16,16,16,__nv_bfloat16,wmma::row_major> af[2];
            wmma::fragment<wmma::matrix_b,16,16,16,__nv_bfloat16,wmma::col_major> bf[4];
            #pragma unroll
            for (int i = 0; i < 2; i++)
                wmma::load_matrix_sync(af[i], Asb + (wm*32 + i*16)*WLD + ks*16, WLD);
            #pragma unroll
            for (int j = 0; j < 4; j++)
                wmma::load_matrix_sync(bf[j], Bsb + (wn*64 + j*16)*WLD + ks*16, WLD);
            #pragma unroll
            for (int i = 0; i < 2; i++)
                #pragma unroll
                for (int j = 0; j < 4; j++)
                    wmma::mma_sync(c[i][j], af[i], bf[j], c[i][j]);
        }
        __syncthreads();
    }
    #pragma unroll
    for (int i = 0; i < 2; i++) {
        #pragma unroll
        for (int j = 0; j < 4; j++) {
            wmma::store_matrix_sync(stage + wid*256, c[i][j], 16, wmma::mem_row_major);
            __syncwarp();
            #pragma unroll
            for (int e = 0; e < 8; e++) {
                int idx = lane + e*32;
                int r = idx >> 4, cc = idx & 15;
                int grow = bm + wm*32 + i*16 + r;
                int gcol = bn + wn*64 + j*16 + cc;
                float v = stage[wid*256 + r*16 + cc] + bias[gcol];
                if (gelu) v = gelu_exact(v);
                if (C32) C32[(size_t)grow*N + gcol] = v;
                if (C16) C16[(size_t)grow*N + gcol] = __float2bfloat16(v);
            }
            __syncwarp();
        }
    }
}

// ---- naive fp32 gemm for tiny head shapes ----
__global__ void gemm_naive(const float* __restrict__ A, const float* __restrict__ W,
                           const float* __restrict__ bias, float* __restrict__ Cf,
                           __nv_bfloat16* __restrict__ Cb, int N, int K, int gelu) {
    int idx = blockIdx.x*256 + threadIdx.x;
    int row = idx / N, col = idx - row*N;
    float s = bias[col];
    const float* a = A + (size_t)row*K;
    for (int k = 0; k < K; k++) s = fmaf(a[k], W[(size_t)k*N + col], s);
    if (gelu) s = gelu_exact(s);
    if (Cf) Cf[idx] = s;
    if (Cb) Cb[idx] = __float2bfloat16(s);
}

// ---- flash v4: FA2-style mma.m16n8k16 bf16, QT=128, KC=64 ----
#define FQT 128
#define FKC 64
#define FQP 136
#define F4_K 34816
#define F4_V 52224
#define FLASH4_SMEM 69632

__global__ __launch_bounds__(256) void flash4(const __nv_bfloat16* __restrict__ qkv,
                                              __nv_bfloat16* __restrict__ out16) {
    __nv_bfloat16* Qs = (__nv_bfloat16*)dynsm;
    __nv_bfloat16* Ks = (__nv_bfloat16*)(dynsm + F4_K);
    __nv_bfloat16* Vs = (__nv_bfloat16*)(dynsm + F4_V);
    const int tid = threadIdx.x, wid = tid >> 5, lane = tid & 31;
    const int g = lane >> 2, tg = lane & 3;
    const int n0 = blockIdx.x*FQT, hh = blockIdx.y;
    const int t0 = n0 & (SEQ - 1), bb = n0 >> 11;
    const int wrow = wid*16;

    // load Q tile: 128 rows x 128 bf16 -> smem (stride 136)
    {
        int r = tid >> 1, c0 = (tid & 1)*64;
        const __nv_bfloat16* qp = qkv + (size_t)(n0 + r)*1536 + hh*DHEAD + c0;
        __nv_bfloat16* qd = Qs + r*FQP + c0;
        #pragma unroll
        for (int q = 0; q < 8; q++) *(uint4*)(qd + q*8) = *(const uint4*)(qp + q*8);
    }
    __syncthreads();
    // Q a-frags (persistent): 8 d-steps x 4 regs
    uint32_t aq[8][4];
    {
        int row = wrow + ((lane >> 3) & 1)*8 + (lane & 7);
        int colb = (lane >> 4)*8;
        #pragma unroll
        for (int s = 0; s < 8; s++)
            ldsm_x4(aq[s][0], aq[s][1], aq[s][2], aq[s][3],
                    smem_u32(Qs + row*FQP + s*16 + colb));
    }

    float o[16][4];
    #pragma unroll
    for (int f = 0; f < 16; f++) { o[f][0]=0; o[f][1]=0; o[f][2]=0; o[f][3]=0; }
    float m0 = -1e30f, m1 = -1e30f, l0 = 0.0f, l1 = 0.0f;
    const int tr0 = t0 + wrow + g, tr1 = tr0 + 8;

    int jstart = t0 - (WINDOW - 1); if (jstart < 0) jstart = 0;
    const int tmax = t0 + FQT - 1;

    for (int jc = jstart; jc <= tmax; jc += FKC) {
        __syncthreads();
        // load K/V chunk: 64 rows x 128 bf16 each
        {
            int r = tid >> 2, c0 = (tid & 3)*32;
            int ja = jc + r; if (ja > tmax) ja = tmax;
            const __nv_bfloat16* kp = qkv + (size_t)((bb << 11) + ja)*1536 + HID + hh*DHEAD + c0;
            __nv_bfloat16* kd = Ks + r*FQP + c0;
            __nv_bfloat16* vd = Vs + r*FQP + c0;
            #pragma unroll
            for (int q = 0; q < 4; q++) {
                *(uint4*)(kd + q*8) = *(const uint4*)(kp + q*8);
                *(uint4*)(vd + q*8) = *(const uint4*)(kp + HID + q*8);
            }
        }
        __syncthreads();

        // S = Q @ K^T : per warp 16 rows x 64 keys
        float sc[8][4];
        #pragma unroll
        for (int f = 0; f < 8; f++) { sc[f][0]=0; sc[f][1]=0; sc[f][2]=0; sc[f][3]=0; }
        {
            int krow_b = ((lane >> 4) & 1)*8 + (lane & 7);
            int kcol_b = ((lane >> 3) & 1)*8;
            #pragma unroll
            for (int ks = 0; ks < 8; ks++) {
                #pragma unroll
                for (int ng = 0; ng < 4; ng++) {
                    uint32_t r0, r1, r2, r3;
                    ldsm_x4(r0, r1, r2, r3,
                            smem_u32(Ks + (ng*16 + krow_b)*FQP + ks*16 + kcol_b));
                    mma16816(sc[2*ng],   aq[ks], r0, r1);
                    mma16816(sc[2*ng+1], aq[ks], r2, r3);
                }
            }
        }

        // mask + scale + row max
        float r0max = -1e30f, r1max = -1e30f;
        #pragma unroll
        for (int f = 0; f < 8; f++) {
            int jb = jc + f*8 + tg*2;
            #pragma unroll
            for (int c = 0; c < 2; c++) {
                int ja = jb + c;
                bool ok0 = (ja <= tr0) && (ja > tr0 - WINDOW);
                bool ok1 = (ja <= tr1) && (ja > tr1 - WINDOW);
                sc[f][c]   = ok0 ? sc[f][c]*SM_SCALE   : -1e30f;
                sc[f][2+c] = ok1 ? sc[f][2+c]*SM_SCALE : -1e30f;
                r0max = fmaxf(r0max, sc[f][c]);
                r1max = fmaxf(r1max, sc[f][2+c]);
            }
        }
        r0max = fmaxf(r0max, __shfl_xor_sync(0xffffffffu, r0max, 1));
        r0max = fmaxf(r0max, __shfl_xor_sync(0xffffffffu, r0max, 2));
        r1max = fmaxf(r1max, __shfl_xor_sync(0xffffffffu, r1max, 1));
        r1max = fmaxf(r1max, __shfl_xor_sync(0xffffffffu, r1max, 2));
        float mc0 = fmaxf(m0, r0max), mc1 = fmaxf(m1, r1max);
        float ls0 = 0.0f, ls1 = 0.0f;
        #pragma unroll
        for (int f = 0; f < 8; f++) {
            #pragma unroll
            for (int c = 0; c < 2; c++) {
                float p0 = (sc[f][c]   <= -1e29f) ? 0.0f : __expf(sc[f][c]   - mc0);
                float p1 = (sc[f][2+c] <= -1e29f) ? 0.0f : __expf(sc[f][2+c] - mc1);
                sc[f][c] = p0; sc[f][2+c] = p1;
                ls0 += p0; ls1 += p1;
            }
        }
        ls0 += __shfl_xor_sync(0xffffffffu, ls0, 1);
        ls0 += __shfl_xor_sync(0xffffffffu, ls0, 2);
        ls1 += __shfl_xor_sync(0xffffffffu, ls1, 1);
        ls1 += __shfl_xor_sync(0xffffffffu, ls1, 2);
        float s0 = __expf(m0 - mc0), s1 = __expf(m1 - mc1);
        l0 = l0*s0 + ls0; l1 = l1*s1 + ls1;
        m0 = mc0; m1 = mc1;

        // rescale O accumulators
        #pragma unroll
        for (int f = 0; f < 16; f++) {
            o[f][0] *= s0; o[f][1] *= s0; o[f][2] *= s1; o[f][3] *= s1;
        }
        // pack P to bf16 a-frags: 4 k-steps
        uint32_t pa[4][4];
        #pragma unroll
        for (int s = 0; s < 4; s++) {
            pa[s][0] = packbf(sc[2*s][0],   sc[2*s][1]);
            pa[s][1] = packbf(sc[2*s][2],   sc[2*s][3]);
            pa[s][2] = packbf(sc[2*s+1][0], sc[2*s+1][1]);
            pa[s][3] = packbf(sc[2*s+1][2], sc[2*s+1][3]);
        }
        // O += P @ V
        {
            int vrow_b = ((lane >> 3) & 1)*8 + (lane & 7);
            int vcol_b = (lane >> 4)*8;
            #pragma unroll
            for (int s = 0; s < 4; s++) {
                #pragma unroll
                for (int ng = 0; ng < 8; ng++) {
                    uint32_t r0, r1, r2, r3;
                    ldsm_x4_t(r0, r1, r2, r3,
                              smem_u32(Vs + (s*16 + vrow_b)*FQP + ng*16 + vcol_b));
                    mma16816(o[2*ng],   pa[s], r0, r1);
                    mma16816(o[2*ng+1], pa[s], r2, r3);
                }
            }
        }
    }

    float inv0 = 1.0f / l0, inv1 = 1.0f / l1;
    __nv_bfloat16* ob0 = out16 + (size_t)(n0 + wrow + g)*HID + hh*DHEAD + tg*2;
    __nv_bfloat16* ob1 = out16 + (size_t)(n0 + wrow + 8 + g)*HID + hh*DHEAD + tg*2;
    #pragma unroll
    for (int f = 0; f < 16; f++) {
        *(uint32_t*)(ob0 + f*8) = packbf(o[f][0]*inv0, o[f][1]*inv0);
        *(uint32_t*)(ob1 + f*8) = packbf(o[f][2]*inv1, o[f][3]*inv1);
    }
}

// ---- residual + LayerNorm (dual write) ----
__global__ __launch_bounds__(256) void ln_kernel(float* __restrict__ x,
                                                 const float* __restrict__ add,
                                                 const float* __restrict__ g,
                                                 const float* __restrict__ b,
                                                 __nv_bfloat16* __restrict__ x16) {
    const int n = blockIdx.x, tid = threadIdx.x;
    const int c0 = tid, c1 = tid + 256;
    float v0 = x[(size_t)n*HID + c0];
    float v1 = x[(size_t)n*HID + c1];
    if (add) { v0 += add[(size_t)n*HID + c0]; v1 += add[(size_t)n*HID + c1]; }
    float s = v0 + v1, sq = v0*v0 + v1*v1;
    #pragma unroll
    for (int o = 16; o > 0; o >>= 1) {
        s  += __shfl_xor_sync(0xffffffffu, s,  o);
        sq += __shfl_xor_sync(0xffffffffu, sq, o);
    }
    __shared__ float ss[8], qq[8], shm, shr;
    int w = tid >> 5;
    if ((tid & 31) == 0) { ss[w] = s; qq[w] = sq; }
    __syncthreads();
    if (tid == 0) {
        float S = 0, Q = 0;
        #pragma unroll
        for (int i = 0; i < 8; i++) { S += ss[i]; Q += qq[i]; }
        float mean = S * (1.0f/512.0f);
        shm = mean;
        shr = rsqrtf(Q * (1.0f/512.0f) - mean*mean + LN_EPS);
    }
    __syncthreads();
    float mean = shm, rstd = shr;
    float o0 = (v0 - mean) * rstd * g[c0] + b[c0];
    float o1 = (v1 - mean) * rstd * g[c1] + b[c1];
    x[(size_t)n*HID + c0] = o0;
    x[(size_t)n*HID + c1] = o1;
    x16[(size_t)n*HID + c0] = __float2bfloat16(o0);
    x16[(size_t)n*HID + c1] = __float2bfloat16(o1);
}

// ---- loss ----
__global__ __launch_bounds__(1024) void loss_kernel(const float* __restrict__ yhat,
                                                    const float* __restrict__ y,
                                                    float* __restrict__ out) {
    float s = 0.0f;
    for (int e = threadIdx.x; e < NTOK*8; e += 1024) {
        int n = e >> 3, d = e & 7;
        int b = n >> 11, t = n & (SEQ - 1);
        float diff = yhat[e] - y[(size_t)(b*8 + d)*SEQ + t];
        s = fmaf(diff, diff, s);
    }
    #pragma unroll
    for (int o = 16; o > 0; o >>= 1) s += __shfl_xor_sync(0xffffffffu, s, o);
    __shared__ float red[32];
    int w = threadIdx.x >> 5;
    if ((threadIdx.x & 31) == 0) red[w] = s;
    __syncthreads();
    if (threadIdx.x == 0) {
        float tot = 0;
        #pragma unroll
        for (int i = 0; i < 32; i++) tot += red[i];
        out[0] = tot;
    }
}

// ---- host ----
static inline void run_wm(const __nv_bfloat16* A, const __nv_bfloat16* B, const float* bias,
                          float* C32, __nv_bfloat16* C16, int N, int K, int gelu) {
    gemm_wmma<<<dim3(N/128, NTOK/128), 256, GEMM_SMEM>>>(A, B, bias, C32, C16, N, K, gelu);
}

extern "C" void kernel_launch(void* const* d_in, const int* in_sizes, int n_in,
                              void* d_out, int out_size) {
    const float *u = (const float*)d_in[0], *y = (const float*)d_in[1];
    const float *W_in = (const float*)d_in[2], *b_in = (const float*)d_in[3];
    const float *qkv_w = (const float*)d_in[4], *qkv_b = (const float*)d_in[5];
    const float *out_w = (const float*)d_in[6], *out_b = (const float*)d_in[7];
    const float *ff1_w = (const float*)d_in[8], *ff1_b = (const float*)d_in[9];
    const float *ff2_w = (const float*)d_in[10], *ff2_b = (const float*)d_in[11];
    const float *ln1_g = (const float*)d_in[12], *ln1_b = (const float*)d_in[13];
    const float *ln2_g = (const float*)d_in[14], *ln2_b = (const float*)d_in[15];
    const float *lnf_g = (const float*)d_in[16], *lnf_b = (const float*)d_in[17];
    const float *xm1_w = (const float*)d_in[18], *xm1_b = (const float*)d_in[19];
    const float *xm2_w = (const float*)d_in[20], *xm2_b = (const float*)d_in[21];
    const float *me1_w = (const float*)d_in[22], *me1_b = (const float*)d_in[23];
    const float *me2_w = (const float*)d_in[24], *me2_b = (const float*)d_in[25];
    const float *me3_w = (const float*)d_in[26], *me3_b = (const float*)d_in[27];

    static float *px = nullptr, *pf32, *pt2, *psmall, *pyhat;
    static __nv_bfloat16 *pqkv16, *px16, *pattn16, *pmid16, *pwt;
    if (!px) {
        cudaGetSymbolAddress((void**)&px, g_x);
        cudaGetSymbolAddress((void**)&pf32, g_f32);
        cudaGetSymbolAddress((void**)&pt2, g_t2);
        cudaGetSymbolAddress((void**)&psmall, g_small);
        cudaGetSymbolAddress((void**)&pyhat, g_yhat);
        cudaGetSymbolAddress((void**)&pqkv16, g_qkv16);
        cudaGetSymbolAddress((void**)&px16, g_x16);
        cudaGetSymbolAddress((void**)&pattn16, g_attn16);
        cudaGetSymbolAddress((void**)&pmid16, g_mid16);
        cudaGetSymbolAddress((void**)&pwt, g_wt);
        cudaFuncSetAttribute(flash4, cudaFuncAttributeMaxDynamicSharedMemorySize, FLASH4_SMEM);
        cudaFuncSetAttribute(gemm_wmma, cudaFuncAttributeMaxDynamicSharedMemorySize, GEMM_SMEM);
    }

    dim3 tb(32, 8);
    // launches 1-3 (so launch #6 = flash4, which ncu -s 5 -c 1 captures)
    wtrans<<<dim3(16, 48, 4), tb>>>(qkv_w, pwt + OFF_QKV, 512, 1536);
    wtrans<<<dim3(16, 16, 4), tb>>>(out_w, pwt + OFF_OUT, 512, 512);
    wtrans<<<dim3(16, 64, 4), tb>>>(ff1_w, pwt + OFF_FF1, 512, 2048);
    embed_kernel<<<NTOK, HID>>>(u, y, W_in, b_in, px, px16);           // 4

    for (int l = 0; l < NLAYER; l++) {
        run_wm(px16, pwt + OFF_QKV + (size_t)l*1536*512, qkv_b + l*1536, nullptr, pqkv16, 1536, 512, 0);  // 5
        flash4<<<dim3(NTOK/FQT, NHEAD), 256, FLASH4_SMEM>>>(pqkv16, pattn16);                             // 6
        if (l == 0)
            wtrans<<<dim3(64, 16, 4), tb>>>(ff2_w, pwt + OFF_FF2, 2048, 512);
        run_wm(pattn16, pwt + OFF_OUT + (size_t)l*512*512, out_b + l*512, pt2, nullptr, 512, 512, 0);
        ln_kernel<<<NTOK, 256>>>(px, pt2, ln1_g + l*HID, ln1_b + l*HID, px16);
        run_wm(px16, pwt + OFF_FF1 + (size_t)l*512*2048, ff1_b + l*2048, nullptr, pmid16, 2048, 512, 1);
        run_wm(pmid16, pwt + OFF_FF2 + (size_t)l*2048*512, ff2_b + l*512, pt2, nullptr, 512, 2048, 0);
        ln_kernel<<<NTOK, 256>>>(px, pt2, ln2_g + l*HID, ln2_b + l*HID, px16);
    }
    ln_kernel<<<NTOK, 256>>>(px, nullptr, lnf_g, lnf_b, px16);

    wtrans<<<dim3(16, 16, 1), tb>>>(xm1_w, pwt + OFF_XM1, 512, 512);
    wtrans<<<dim3(16, 16, 1), tb>>>(me2_w, pwt + OFF_ME2, 512, 512);
    run_wm(px16, pwt + OFF_XM1, xm1_b, pt2, nullptr, 512, 512, 1);
    gemm_naive<<<NTOK*16/256, 256>>>(pt2, xm2_w, xm2_b, psmall, nullptr, 16, 512, 0);
    gemm_naive<<<NTOK*512/256, 256>>>(psmall, me1_w, me1_b, nullptr, pattn16, 512, 16, 1);
    run_wm(pattn16, pwt + OFF_ME2, me2_b, pf32, nullptr, 512, 512, 1);
    gemm_naive<<<NTOK*8/256, 256>>>(pf32, me3_w, me3_b, pyhat, nullptr, 8, 512, 0);

    loss_kernel<<<1, 1024>>>(pyhat, y, (float*)d_out);
}